// round 7
// baseline (speedup 1.0000x reference)
#include <cuda_runtime.h>
#include <cuda_bf16.h>
#include <math.h>
#include <stdint.h>

#define BB 32
#define NN 512
#define HH 128

// h split-bf16 planes, [b][d][n] (transposed), row-contiguous in n. 4 MB each.
__device__ __nv_bfloat16 g_hBhi[BB * HH * NN];
__device__ __nv_bfloat16 g_hBlo[BB * HH * NN];

__device__ __forceinline__ uint32_t smem_u32(const void* p) {
    uint32_t a;
    asm("{ .reg .u64 t; cvta.to.shared.u64 t, %1; cvt.u32.u64 %0, t; }"
        : "=r"(a) : "l"(p));
    return a;
}

#define CP_ASYNC16(dst_u32, src_ptr) \
    asm volatile("cp.async.cg.shared.global [%0], [%1], 16;" \
                 :: "r"(dst_u32), "l"(src_ptr) : "memory")
#define CP_COMMIT() asm volatile("cp.async.commit_group;" ::: "memory")
#define CP_WAIT(n)  asm volatile("cp.async.wait_group %0;" :: "n"(n) : "memory")

// ---------------------------------------------------------------------------
// K1: h = silu(LN(s @ W1^T + b1)); writes transposed split-bf16 planes.
// 256 CTAs x 256 thr; 64 rows/CTA; thread tile 4 rows x 8 cols.
// smem: W1T[128][132] f32 | sA[128 h][66 r] f32 (reused as hp[64][132]) |
//       tr[128 d][66 n] u32.  Total 135168 B.
// ---------------------------------------------------------------------------
__global__ void __launch_bounds__(256)
k1_lin_ln_silu(const float* __restrict__ s,
               const float* __restrict__ W1,
               const float* __restrict__ b1) {
    extern __shared__ float smem[];
    float*    W1T = smem;                            // 128*132
    float*    sA  = smem + 128 * 132;                // 128*66 (reused as hp 64*132)
    uint32_t* tr  = (uint32_t*)(sA + 128 * 66);      // 128*66 u32

    const int t    = threadIdx.x;
    const int row0 = blockIdx.x * 64;
    const int lane = t & 31;
    const int wid  = t >> 5;
    const int cg   = t & 15;     // 8-col group
    const int rg   = t >> 4;     // 4-row group

#pragma unroll 8
    for (int k = 0; k < 64; ++k) {
        int u = t + k * 256;
        int c = u >> 7, h = u & 127;
        W1T[h * 132 + c] = W1[u];
    }
#pragma unroll 8
    for (int k = 0; k < 32; ++k) {
        int u = t + k * 256;             // 0..8191
        int r = u >> 7, h = u & 127;
        sA[h * 66 + r] = s[row0 * 128 + u];
    }
    __syncthreads();

    float acc[4][8];
#pragma unroll
    for (int rr = 0; rr < 4; ++rr)
#pragma unroll
        for (int cc = 0; cc < 8; ++cc) acc[rr][cc] = 0.0f;

    const float4* W1T4 = (const float4*)W1T;   // row stride 33 float4
#pragma unroll 2
    for (int h = 0; h < 128; ++h) {
        float4 w0 = W1T4[h * 33 + cg * 2];
        float4 w1 = W1T4[h * 33 + cg * 2 + 1];
        float av[4];
#pragma unroll
        for (int rr = 0; rr < 4; ++rr) av[rr] = sA[h * 66 + rg * 4 + rr];
#pragma unroll
        for (int rr = 0; rr < 4; ++rr) {
            acc[rr][0] += av[rr] * w0.x; acc[rr][1] += av[rr] * w0.y;
            acc[rr][2] += av[rr] * w0.z; acc[rr][3] += av[rr] * w0.w;
            acc[rr][4] += av[rr] * w1.x; acc[rr][5] += av[rr] * w1.y;
            acc[rr][6] += av[rr] * w1.z; acc[rr][7] += av[rr] * w1.w;
        }
    }
    {
        float4 bv0 = ((const float4*)b1)[cg * 2];
        float4 bv1 = ((const float4*)b1)[cg * 2 + 1];
#pragma unroll
        for (int rr = 0; rr < 4; ++rr) {
            acc[rr][0] += bv0.x; acc[rr][1] += bv0.y; acc[rr][2] += bv0.z; acc[rr][3] += bv0.w;
            acc[rr][4] += bv1.x; acc[rr][5] += bv1.y; acc[rr][6] += bv1.z; acc[rr][7] += bv1.w;
        }
    }

    __syncthreads();            // sA reads done -> reuse as hp
    float4* hp4 = (float4*)sA;  // [64 rows][33 float4] (132-float stride)
#pragma unroll
    for (int rr = 0; rr < 4; ++rr) {
        int row = rg * 4 + rr;
        hp4[row * 33 + cg * 2]     = make_float4(acc[rr][0], acc[rr][1], acc[rr][2], acc[rr][3]);
        hp4[row * 33 + cg * 2 + 1] = make_float4(acc[rr][4], acc[rr][5], acc[rr][6], acc[rr][7]);
    }
    __syncthreads();

    const float inv128 = 1.0f / 128.0f;
#pragma unroll
    for (int rr = 0; rr < 8; ++rr) {
        int row = wid * 8 + rr;
        float4 x = hp4[row * 33 + lane];
        float sm = x.x + x.y + x.z + x.w;
        float sq = x.x * x.x + x.y * x.y + x.z * x.z + x.w * x.w;
#pragma unroll
        for (int o = 16; o > 0; o >>= 1) {
            sm += __shfl_xor_sync(0xFFFFFFFFu, sm, o);
            sq += __shfl_xor_sync(0xFFFFFFFFu, sq, o);
        }
        float mu  = sm * inv128;
        float var = sq * inv128 - mu * mu;
        float rs  = rsqrtf(var + 1e-5f);
        float y[4];
        y[0] = (x.x - mu) * rs; y[1] = (x.y - mu) * rs;
        y[2] = (x.z - mu) * rs; y[3] = (x.w - mu) * rs;
#pragma unroll
        for (int q = 0; q < 4; ++q) {
            float yv = y[q] / (1.0f + __expf(-y[q]));    // silu
            __nv_bfloat16 hi = __float2bfloat16(yv);
            __nv_bfloat16 lo = __float2bfloat16(yv - __bfloat162float(hi));
            uint32_t pk = (uint32_t)__bfloat16_as_ushort(hi)
                        | ((uint32_t)__bfloat16_as_ushort(lo) << 16);
            tr[(lane * 4 + q) * 66 + row] = pk;
        }
    }
    __syncthreads();

    // store split planes: 128 d x 32 n-pairs
    const int b  = blockIdx.x >> 3;
    const int n0 = (blockIdx.x & 7) * 64;
#pragma unroll
    for (int k = 0; k < 16; ++k) {
        int u = t + k * 256;              // 0..4095
        int d = u >> 5, np = u & 31;
        uint32_t t0 = tr[d * 66 + 2 * np];
        uint32_t t1 = tr[d * 66 + 2 * np + 1];
        uint32_t hip = (t0 & 0xFFFFu) | (t1 << 16);
        uint32_t lop = (t0 >> 16) | (t1 & 0xFFFF0000u);
        int idx = ((b * 128 + d) * 512 + n0) / 2 + np;
        ((uint32_t*)g_hBhi)[idx] = hip;
        ((uint32_t*)g_hBlo)[idx] = lop;
    }
}

// ---------------------------------------------------------------------------
// K2: fully-overlapped split-bf16 HMMA CFConv.
// grid: 32 b x 8 i-tiles (64 i) = 256 CTAs, 512 threads (16 warps 4m x 4n).
// Double-buffered conv tiles; no raw staging. Per phase ch:
//   issue cp.async B(ch+1) -> B[1-p];  LDG ev/mk(ch+1) half0 -> regs
//   MMA kb0,kb1 (from A[p],B[p]);  convert half0 -> A[1-p]; LDG half1
//   MMA kb2,kb3;  convert half1 -> A[1-p];  cp.wait; barrier
// smem: A[2][3c][2split][64 i][144B] = 110592 B; B[2][2split][128 d][144B]
//       @110592 = 73728 B.  Total 184320 B.
// ---------------------------------------------------------------------------
#define A_BUF_STRIDE 55296
#define A_C_STRIDE   18432
#define A_S_STRIDE   9216
#define SM_ROW       144
#define B_BASE       110592
#define B_BUF_STRIDE 36864
#define B_S_STRIDE   18432
#define K2_SMEM      184320

#define LDSM_X4(r, addr) \
    asm volatile("ldmatrix.sync.aligned.m8n8.x4.shared.b16 {%0,%1,%2,%3}, [%4];" \
                 : "=r"((r)[0]), "=r"((r)[1]), "=r"((r)[2]), "=r"((r)[3]) \
                 : "r"(addr))

#define MMA_BF16(acc, a, b0, b1) \
    asm volatile("mma.sync.aligned.m16n8k16.row.col.f32.bf16.bf16.f32 " \
                 "{%0,%1,%2,%3}, {%4,%5,%6,%7}, {%8,%9}, {%0,%1,%2,%3};" \
                 : "+f"((acc)[0]), "+f"((acc)[1]), "+f"((acc)[2]), "+f"((acc)[3]) \
                 : "r"((a)[0]), "r"((a)[1]), "r"((a)[2]), "r"((a)[3]), \
                   "r"(b0), "r"(b1))

__global__ void __launch_bounds__(512, 1)
k2_cfconv_mma(const float* __restrict__ ev,
              const float* __restrict__ mask,
              float* __restrict__ out) {
    extern __shared__ char smc[];
    const uint32_t smem_base = smem_u32(smc);
    const int t    = threadIdx.x;
    const int lane = t & 31;
    const int wid  = t >> 5;
    const int wm   = wid >> 2;     // 0..3: i-subtile of 16
    const int wn   = wid & 3;      // 0..3: d-subtile of 32
    const int b    = blockIdx.x >> 3;
    const int i0   = (blockIdx.x & 7) * 64;

    // convert ownership: thread -> (i, jb) ; covers 8 j for all 3 c
    const int cv_i  = t >> 3;
    const int cv_jb = t & 7;
    const float* ev_row = ev + ((size_t)((b * 512 + i0 + cv_i) * 512)) * 3 + cv_jb * 24;
    const float* mk_row = mask + (size_t)(b * 512 + i0 + cv_i) * 512 + cv_jb * 8;
    const uint32_t cv_dst = (uint32_t)(cv_i * SM_ROW + cv_jb * 16);

    float acc[3][4][4];
#pragma unroll
    for (int c = 0; c < 3; ++c)
#pragma unroll
        for (int nt = 0; nt < 4; ++nt)
#pragma unroll
            for (int q = 0; q < 4; ++q) acc[c][nt][q] = 0.0f;

    const uint32_t a_lane = (uint32_t)((wm * 16 + (lane & 15)) * SM_ROW + (lane >> 4) * 16);
    uint32_t b_lane[2];
#pragma unroll
    for (int q = 0; q < 2; ++q) {
        int n = wn * 32 + q * 16 + (lane & 7) + ((lane >> 4) & 1) * 8;
        b_lane[q] = (uint32_t)(B_BASE + n * SM_ROW + ((lane >> 3) & 1) * 16);
    }

    // B(ch) -> buffer pb via cp.async (2 splits x 128 d x 128B)
    auto issue_B = [&](int j0, int pb) {
#pragma unroll
        for (int p = t; p < 2048; p += 512) {
            int sp = p >> 10, r = p & 1023;
            int d = r >> 3, q = r & 7;
            const char* srcbase = sp ? (const char*)g_hBlo : (const char*)g_hBhi;
            const char* src = srcbase + ((size_t)((b * 128 + d) * 512 + j0) * 2) + q * 16;
            CP_ASYNC16(smem_base + B_BASE + pb * B_BUF_STRIDE + sp * B_S_STRIDE
                       + d * SM_ROW + q * 16, src);
        }
        CP_COMMIT();
    };

    // LDG one half (4 j) of this thread's (i, jb) block for chunk at j0
    auto ldg_half = [&](int j0, int h, float4* rev, float4& rmk) {
        const float4* ep = (const float4*)(ev_row + (size_t)j0 * 3 + h * 12);
        rev[0] = ep[0]; rev[1] = ep[1]; rev[2] = ep[2];
        rmk = *(const float4*)(mk_row + j0 + h * 4);
    };

    // convert one half into A[pa]
    auto convert_half = [&](int pa, int h, const float4* rev, const float4& rmk) {
        const float* evv = (const float*)rev;   // 12 floats: [j][c]
        float mv[4] = {rmk.x, rmk.y, rmk.z, rmk.w};
#pragma unroll
        for (int c = 0; c < 3; ++c) {
            uint32_t hi2[2], lo2[2];
#pragma unroll
            for (int pr = 0; pr < 2; ++pr) {
                float v0 = evv[(2 * pr)     * 3 + c] * mv[2 * pr];
                float v1 = evv[(2 * pr + 1) * 3 + c] * mv[2 * pr + 1];
                uint32_t vb0 = __float_as_uint(v0), vb1 = __float_as_uint(v1);
                uint32_t h0 = vb0 & 0xFFFF0000u, h1 = vb1 & 0xFFFF0000u;
                float l0f = v0 - __uint_as_float(h0);
                float l1f = v1 - __uint_as_float(h1);
                uint16_t l0 = __bfloat16_as_ushort(__float2bfloat16(l0f));
                uint16_t l1 = __bfloat16_as_ushort(__float2bfloat16(l1f));
                hi2[pr] = (h0 >> 16) | (h1 & 0xFFFF0000u);
                lo2[pr] = (uint32_t)l0 | ((uint32_t)l1 << 16);
            }
            char* dst = smc + pa * A_BUF_STRIDE + c * A_C_STRIDE + cv_dst + h * 8;
            *(uint2*)dst                = make_uint2(hi2[0], hi2[1]);
            *(uint2*)(dst + A_S_STRIDE) = make_uint2(lo2[0], lo2[1]);
        }
    };

    // one kb-step of MMAs from buffers (pa, pb)
    auto mma_kb = [&](int kb, int pa, int pb) {
        uint32_t afr[3][2][4];
        uint32_t bfr[2][2][4];
#pragma unroll
        for (int c = 0; c < 3; ++c)
#pragma unroll
            for (int s = 0; s < 2; ++s)
                LDSM_X4(afr[c][s], smem_base + pa * A_BUF_STRIDE + c * A_C_STRIDE
                                 + s * A_S_STRIDE + a_lane + kb * 32);
#pragma unroll
        for (int s = 0; s < 2; ++s)
#pragma unroll
            for (int q = 0; q < 2; ++q)
                LDSM_X4(bfr[s][q], smem_base + b_lane[q] + pb * B_BUF_STRIDE
                                 + s * B_S_STRIDE + kb * 32);
#pragma unroll
        for (int pass = 0; pass < 3; ++pass) {
            const int as = (pass == 1) ? 1 : 0;
            const int bs = (pass == 2) ? 1 : 0;
#pragma unroll
            for (int c = 0; c < 3; ++c)
#pragma unroll
                for (int nt = 0; nt < 4; ++nt) {
                    uint32_t* bbv = bfr[bs][nt >> 1];
                    MMA_BF16(acc[c][nt], afr[c][as],
                             bbv[(nt & 1) * 2], bbv[(nt & 1) * 2 + 1]);
                }
        }
    };

    // ---- prologue: fill A[0], B[0] for chunk 0
    {
        float4 rev[3]; float4 rmk;
        issue_B(0, 0);
        ldg_half(0, 0, rev, rmk);
        convert_half(0, 0, rev, rmk);
        ldg_half(0, 1, rev, rmk);
        convert_half(0, 1, rev, rmk);
        CP_WAIT(0);
        __syncthreads();
    }

#pragma unroll 1
    for (int ch = 0; ch < 8; ++ch) {
        const int p  = ch & 1;
        const int np = p ^ 1;
        const int nj = (ch + 1) * 64;
        float4 rev[3]; float4 rmk;

        if (ch < 7) {
            issue_B(nj, np);
            ldg_half(nj, 0, rev, rmk);
        }
        mma_kb(0, p, p);
        mma_kb(1, p, p);
        if (ch < 7) {
            convert_half(np, 0, rev, rmk);
            ldg_half(nj, 1, rev, rmk);
        }
        mma_kb(2, p, p);
        mma_kb(3, p, p);
        if (ch < 7) {
            convert_half(np, 1, rev, rmk);
        }
        CP_WAIT(0);
        __syncthreads();
    }

    // ---- epilogue: fragments -> out[b][i][c][d]
    const int r0 = i0 + wm * 16 + (lane >> 2);
    const int dq = wn * 32 + (lane & 3) * 2;
#pragma unroll
    for (int c = 0; c < 3; ++c) {
#pragma unroll
        for (int nt = 0; nt < 4; ++nt) {
            int d = dq + nt * 8;
            size_t o0 = ((size_t)(b * 512 + r0)     * 3 + c) * 128 + d;
            size_t o1 = ((size_t)(b * 512 + r0 + 8) * 3 + c) * 128 + d;
            *(float2*)(out + o0) = make_float2(acc[c][nt][0], acc[c][nt][1]);
            *(float2*)(out + o1) = make_float2(acc[c][nt][2], acc[c][nt][3]);
        }
    }
}

// ---------------------------------------------------------------------------
extern "C" void kernel_launch(void* const* d_in, const int* in_sizes, int n_in,
                              void* d_out, int out_size) {
    const float* s    = (const float*)d_in[0];   // (32,512,128)
    const float* ev   = (const float*)d_in[1];   // (32,512,512,3)
    const float* mask = (const float*)d_in[2];   // (32,512,512,1)
    const float* W1   = (const float*)d_in[3];   // (128,128)
    const float* b1   = (const float*)d_in[4];   // (128,)
    float* out = (float*)d_out;                  // (32,512,3,128)

    const int k1_smem = (128 * 132 + 128 * 66) * (int)sizeof(float)
                      + 128 * 66 * (int)sizeof(uint32_t);   // 135168
    cudaFuncSetAttribute(k1_lin_ln_silu,
                         cudaFuncAttributeMaxDynamicSharedMemorySize, k1_smem);
    cudaFuncSetAttribute(k2_cfconv_mma,
                         cudaFuncAttributeMaxDynamicSharedMemorySize, K2_SMEM);

    k1_lin_ln_silu<<<(BB * NN) / 64, 256, k1_smem>>>(s, W1, b1);
    k2_cfconv_mma<<<BB * 8, 512, K2_SMEM>>>(ev, mask, out);
}

// round 8
// speedup vs baseline: 1.0134x; 1.0134x over previous
#include <cuda_runtime.h>
#include <cuda_bf16.h>
#include <math.h>
#include <stdint.h>

#define BB 32
#define NN 512
#define HH 128

// h split-bf16 planes, [b][d][n] (transposed), row-contiguous in n. 4 MB each.
__device__ __nv_bfloat16 g_hBhi[BB * HH * NN];
__device__ __nv_bfloat16 g_hBlo[BB * HH * NN];

__device__ __forceinline__ uint32_t smem_u32(const void* p) {
    uint32_t a;
    asm("{ .reg .u64 t; cvta.to.shared.u64 t, %1; cvt.u32.u64 %0, t; }"
        : "=r"(a) : "l"(p));
    return a;
}

#define CP_ASYNC16(dst_u32, src_ptr) \
    asm volatile("cp.async.cg.shared.global [%0], [%1], 16;" \
                 :: "r"(dst_u32), "l"(src_ptr) : "memory")
#define CP_COMMIT() asm volatile("cp.async.commit_group;" ::: "memory")
#define CP_WAIT(n)  asm volatile("cp.async.wait_group %0;" :: "n"(n) : "memory")

// ---------------------------------------------------------------------------
// K1 (reverted to R6 version — conflict-free): h = silu(LN(s @ W1^T + b1));
// 256 CTAs x 256 thr; each CTA: 64 rows as two 32-row tiles, W1T loaded once.
// ---------------------------------------------------------------------------
__global__ void __launch_bounds__(256)
k1_lin_ln_silu(const float* __restrict__ s,
               const float* __restrict__ W1,
               const float* __restrict__ b1) {
    extern __shared__ float smem[];
    float*    W1T = smem;                           // 128*132 floats
    float*    sT  = smem + 128 * 132;               // 128*33 floats (reused as hp)
    uint32_t* tr  = (uint32_t*)(smem + 128 * 132 + 128 * 33);  // 128*33 u32

    const int t    = threadIdx.x;
    const int row0 = blockIdx.x * 64;
    const int cg = t & 31;
    const int rg = t >> 5;

#pragma unroll 8
    for (int k = 0; k < 64; ++k) {
        int u = t + k * 256;
        int c = u >> 7, h = u & 127;
        W1T[h * 132 + c] = W1[u];
    }

    for (int rt = 0; rt < 2; ++rt) {
        const int rbase = row0 + rt * 32;
        __syncthreads();          // prev tile fully consumed
#pragma unroll 8
        for (int k = 0; k < 16; ++k) {
            int u = t + k * 256;
            int r = u >> 7, h = u & 127;
            sT[h * 33 + r] = s[rbase * 128 + u];
        }
        __syncthreads();

        float4 acc0 = make_float4(0.f, 0.f, 0.f, 0.f);
        float4 acc1 = acc0, acc2 = acc0, acc3 = acc0;

        const float4* W1T4 = (const float4*)W1T;
#pragma unroll 4
        for (int h = 0; h < 128; ++h) {
            float4 w = W1T4[h * 33 + cg];
            float a0 = sT[h * 33 + rg * 4 + 0];
            float a1 = sT[h * 33 + rg * 4 + 1];
            float a2 = sT[h * 33 + rg * 4 + 2];
            float a3 = sT[h * 33 + rg * 4 + 3];
            acc0.x += a0 * w.x; acc0.y += a0 * w.y; acc0.z += a0 * w.z; acc0.w += a0 * w.w;
            acc1.x += a1 * w.x; acc1.y += a1 * w.y; acc1.z += a1 * w.z; acc1.w += a1 * w.w;
            acc2.x += a2 * w.x; acc2.y += a2 * w.y; acc2.z += a2 * w.z; acc2.w += a2 * w.w;
            acc3.x += a3 * w.x; acc3.y += a3 * w.y; acc3.z += a3 * w.z; acc3.w += a3 * w.w;
        }
        {
            float4 bv = ((const float4*)b1)[cg];
            acc0.x += bv.x; acc0.y += bv.y; acc0.z += bv.z; acc0.w += bv.w;
            acc1.x += bv.x; acc1.y += bv.y; acc1.z += bv.z; acc1.w += bv.w;
            acc2.x += bv.x; acc2.y += bv.y; acc2.z += bv.z; acc2.w += bv.w;
            acc3.x += bv.x; acc3.y += bv.y; acc3.z += bv.z; acc3.w += bv.w;
        }

        __syncthreads();          // sT reads done -> reuse as hp
        float4* hp4 = (float4*)sT;    // [32 rows][32 float4]
        hp4[(rg * 4 + 0) * 32 + cg] = acc0;
        hp4[(rg * 4 + 1) * 32 + cg] = acc1;
        hp4[(rg * 4 + 2) * 32 + cg] = acc2;
        hp4[(rg * 4 + 3) * 32 + cg] = acc3;
        __syncthreads();

        const float inv128 = 1.0f / 128.0f;
#pragma unroll
        for (int rr = 0; rr < 4; ++rr) {
            int row = rg * 4 + rr;
            float4 x = hp4[row * 32 + cg];
            float sm = x.x + x.y + x.z + x.w;
            float sq = x.x * x.x + x.y * x.y + x.z * x.z + x.w * x.w;
#pragma unroll
            for (int o = 16; o > 0; o >>= 1) {
                sm += __shfl_xor_sync(0xFFFFFFFFu, sm, o);
                sq += __shfl_xor_sync(0xFFFFFFFFu, sq, o);
            }
            float mu  = sm * inv128;
            float var = sq * inv128 - mu * mu;
            float rs  = rsqrtf(var + 1e-5f);
            float y[4];
            y[0] = (x.x - mu) * rs; y[1] = (x.y - mu) * rs;
            y[2] = (x.z - mu) * rs; y[3] = (x.w - mu) * rs;
#pragma unroll
            for (int q = 0; q < 4; ++q) {
                float yv = y[q] / (1.0f + __expf(-y[q]));    // silu
                __nv_bfloat16 hi = __float2bfloat16(yv);
                __nv_bfloat16 lo = __float2bfloat16(yv - __bfloat162float(hi));
                uint32_t pk = (uint32_t)__bfloat16_as_ushort(hi)
                            | ((uint32_t)__bfloat16_as_ushort(lo) << 16);
                tr[(4 * cg + q) * 33 + row] = pk;
            }
        }
        __syncthreads();

        const int b  = row0 >> 9;
        const int n0 = (row0 & 511) + rt * 32;
#pragma unroll
        for (int k = 0; k < 8; ++k) {
            int u = t + k * 256;              // 0..2047
            int d = u >> 4, np = u & 15;
            uint32_t t0 = tr[d * 33 + 2 * np];
            uint32_t t1 = tr[d * 33 + 2 * np + 1];
            uint32_t hip = (t0 & 0xFFFFu) | (t1 << 16);
            uint32_t lop = (t0 >> 16) | (t1 & 0xFFFF0000u);
            int idx = ((b * 128 + d) * 512 + n0) / 2 + np;
            ((uint32_t*)g_hBhi)[idx] = hip;
            ((uint32_t*)g_hBlo)[idx] = lop;
        }
    }
}

// ---------------------------------------------------------------------------
// K2: split-bf16 HMMA CFConv, 2-CTA/SM cross-overlap.
// grid: 32 b x 16 i-tiles (32 i) = 512 CTAs, 256 threads (8 warps, 2m x 4n).
// smem (101376 B, 2 CTAs/SM):
//   A [3c][2split][32 i][144B]   = 27648 B  (single-buffered; ev/mk via regs)
//   B [2buf][2split][128 d][144B] @27648 = 73728 B (double, cp.async)
// Per chunk: issue B(ch+1)->B[1-p]; LDG ev/mk(ch+1)->regs; MMA(ch); bar;
//            convert(ch+1)->A; cp.wait; bar.
// ---------------------------------------------------------------------------
#define A_C_STRIDE   9216
#define A_S_STRIDE   4608
#define SM_ROW       144
#define B_BASE       27648
#define B_BUF_STRIDE 36864
#define B_S_STRIDE   18432
#define K2_SMEM      101376

#define LDSM_X4(r, addr) \
    asm volatile("ldmatrix.sync.aligned.m8n8.x4.shared.b16 {%0,%1,%2,%3}, [%4];" \
                 : "=r"((r)[0]), "=r"((r)[1]), "=r"((r)[2]), "=r"((r)[3]) \
                 : "r"(addr))

#define MMA_BF16(acc, a, b0, b1) \
    asm volatile("mma.sync.aligned.m16n8k16.row.col.f32.bf16.bf16.f32 " \
                 "{%0,%1,%2,%3}, {%4,%5,%6,%7}, {%8,%9}, {%0,%1,%2,%3};" \
                 : "+f"((acc)[0]), "+f"((acc)[1]), "+f"((acc)[2]), "+f"((acc)[3]) \
                 : "r"((a)[0]), "r"((a)[1]), "r"((a)[2]), "r"((a)[3]), \
                   "r"(b0), "r"(b1))

__global__ void __launch_bounds__(256, 2)
k2_cfconv_mma(const float* __restrict__ ev,
              const float* __restrict__ mask,
              float* __restrict__ out) {
    extern __shared__ char smc[];
    const uint32_t smem_base = smem_u32(smc);
    const int t    = threadIdx.x;
    const int lane = t & 31;
    const int wid  = t >> 5;
    const int wm   = wid >> 2;     // 0..1: i-subtile of 16
    const int wn   = wid & 3;      // 0..3: d-subtile of 32
    const int b    = blockIdx.x >> 4;
    const int i0   = (blockIdx.x & 15) * 32;

    // convert ownership: thread -> (i, jb); covers 8 j for all 3 c
    const int cv_i  = t >> 3;      // 0..31
    const int cv_jb = t & 7;
    const float* ev_row = ev + ((size_t)((b * 512 + i0 + cv_i) * 512)) * 3 + cv_jb * 24;
    const float* mk_row = mask + (size_t)(b * 512 + i0 + cv_i) * 512 + cv_jb * 8;
    const uint32_t cv_dst = (uint32_t)(cv_i * SM_ROW + cv_jb * 16);

    float acc[3][4][4];
#pragma unroll
    for (int c = 0; c < 3; ++c)
#pragma unroll
        for (int nt = 0; nt < 4; ++nt)
#pragma unroll
            for (int q = 0; q < 4; ++q) acc[c][nt][q] = 0.0f;

    const uint32_t a_lane = (uint32_t)((wm * 16 + (lane & 15)) * SM_ROW + (lane >> 4) * 16);
    uint32_t b_lane[2];
#pragma unroll
    for (int q = 0; q < 2; ++q) {
        int n = wn * 32 + q * 16 + (lane & 7) + ((lane >> 4) & 1) * 8;
        b_lane[q] = (uint32_t)(B_BASE + n * SM_ROW + ((lane >> 3) & 1) * 16);
    }

    // B(chunk at j0) -> buffer pb (2 splits x 128 d x 128B = 2048 16B chunks)
    auto issue_B = [&](int j0, int pb) {
#pragma unroll
        for (int p = t; p < 2048; p += 256) {
            int sp = p >> 10, r = p & 1023;
            int d = r >> 3, q = r & 7;
            const char* srcbase = sp ? (const char*)g_hBlo : (const char*)g_hBhi;
            const char* src = srcbase + ((size_t)((b * 128 + d) * 512 + j0) * 2) + q * 16;
            CP_ASYNC16(smem_base + B_BASE + pb * B_BUF_STRIDE + sp * B_S_STRIDE
                       + d * SM_ROW + q * 16, src);
        }
        CP_COMMIT();
    };

    auto ldg_half = [&](int j0, int h, float4* rev, float4& rmk) {
        const float4* ep = (const float4*)(ev_row + (size_t)j0 * 3 + h * 12);
        rev[0] = ep[0]; rev[1] = ep[1]; rev[2] = ep[2];
        rmk = *(const float4*)(mk_row + j0 + h * 4);
    };

    auto convert_half = [&](int h, const float4* rev, const float4& rmk) {
        const float* evv = (const float*)rev;   // 12 floats: [j][c]
        float mv[4] = {rmk.x, rmk.y, rmk.z, rmk.w};
#pragma unroll
        for (int c = 0; c < 3; ++c) {
            uint32_t hi2[2], lo2[2];
#pragma unroll
            for (int pr = 0; pr < 2; ++pr) {
                float v0 = evv[(2 * pr)     * 3 + c] * mv[2 * pr];
                float v1 = evv[(2 * pr + 1) * 3 + c] * mv[2 * pr + 1];
                uint32_t vb0 = __float_as_uint(v0), vb1 = __float_as_uint(v1);
                uint32_t h0 = vb0 & 0xFFFF0000u, h1 = vb1 & 0xFFFF0000u;
                float l0f = v0 - __uint_as_float(h0);
                float l1f = v1 - __uint_as_float(h1);
                uint16_t l0 = __bfloat16_as_ushort(__float2bfloat16(l0f));
                uint16_t l1 = __bfloat16_as_ushort(__float2bfloat16(l1f));
                hi2[pr] = (h0 >> 16) | (h1 & 0xFFFF0000u);
                lo2[pr] = (uint32_t)l0 | ((uint32_t)l1 << 16);
            }
            char* dst = smc + c * A_C_STRIDE + cv_dst + h * 8;
            *(uint2*)dst                = make_uint2(hi2[0], hi2[1]);
            *(uint2*)(dst + A_S_STRIDE) = make_uint2(lo2[0], lo2[1]);
        }
    };

    auto mma_kb = [&](int kb, int pb) {
        uint32_t afr[3][2][4];
        uint32_t bfr[2][2][4];
#pragma unroll
        for (int c = 0; c < 3; ++c)
#pragma unroll
            for (int s = 0; s < 2; ++s)
                LDSM_X4(afr[c][s], smem_base + c * A_C_STRIDE
                                 + s * A_S_STRIDE + a_lane + kb * 32);
#pragma unroll
        for (int s = 0; s < 2; ++s)
#pragma unroll
            for (int q = 0; q < 2; ++q)
                LDSM_X4(bfr[s][q], smem_base + b_lane[q] + pb * B_BUF_STRIDE
                                 + s * B_S_STRIDE + kb * 32);
#pragma unroll
        for (int pass = 0; pass < 3; ++pass) {
            const int as = (pass == 1) ? 1 : 0;
            const int bs = (pass == 2) ? 1 : 0;
#pragma unroll
            for (int c = 0; c < 3; ++c)
#pragma unroll
                for (int nt = 0; nt < 4; ++nt) {
                    uint32_t* bbv = bfr[bs][nt >> 1];
                    MMA_BF16(acc[c][nt], afr[c][as],
                             bbv[(nt & 1) * 2], bbv[(nt & 1) * 2 + 1]);
                }
        }
    };

    float4 rev0[3], rev1[3]; float4 rmk0, rmk1;

    // ---- prologue: fill A(0), B[0]
    issue_B(0, 0);
    ldg_half(0, 0, rev0, rmk0);
    ldg_half(0, 1, rev1, rmk1);
    convert_half(0, rev0, rmk0);
    convert_half(1, rev1, rmk1);
    CP_WAIT(0);
    __syncthreads();

#pragma unroll 1
    for (int ch = 0; ch < 8; ++ch) {
        const int p  = ch & 1;
        const int nj = (ch + 1) * 64;

        if (ch < 7) {
            issue_B(nj, p ^ 1);
            ldg_half(nj, 0, rev0, rmk0);
        }
        mma_kb(0, p);
        mma_kb(1, p);
        if (ch < 7) ldg_half(nj, 1, rev1, rmk1);
        mma_kb(2, p);
        mma_kb(3, p);

        __syncthreads();           // all MMA(ch) done -> A writable
        if (ch < 7) {
            convert_half(0, rev0, rmk0);
            convert_half(1, rev1, rmk1);
        }
        CP_WAIT(0);                // B(ch+1) landed
        __syncthreads();           // A(ch+1)/B ready for all
    }

    // ---- epilogue: fragments -> out[b][i][c][d]
    const int r0 = i0 + wm * 16 + (lane >> 2);
    const int dq = wn * 32 + (lane & 3) * 2;
#pragma unroll
    for (int c = 0; c < 3; ++c) {
#pragma unroll
        for (int nt = 0; nt < 4; ++nt) {
            int d = dq + nt * 8;
            size_t o0 = ((size_t)(b * 512 + r0)     * 3 + c) * 128 + d;
            size_t o1 = ((size_t)(b * 512 + r0 + 8) * 3 + c) * 128 + d;
            *(float2*)(out + o0) = make_float2(acc[c][nt][0], acc[c][nt][1]);
            *(float2*)(out + o1) = make_float2(acc[c][nt][2], acc[c][nt][3]);
        }
    }
}

// ---------------------------------------------------------------------------
extern "C" void kernel_launch(void* const* d_in, const int* in_sizes, int n_in,
                              void* d_out, int out_size) {
    const float* s    = (const float*)d_in[0];   // (32,512,128)
    const float* ev   = (const float*)d_in[1];   // (32,512,512,3)
    const float* mask = (const float*)d_in[2];   // (32,512,512,1)
    const float* W1   = (const float*)d_in[3];   // (128,128)
    const float* b1   = (const float*)d_in[4];   // (128,)
    float* out = (float*)d_out;                  // (32,512,3,128)

    const int k1_smem = (128 * 132 + 128 * 33) * (int)sizeof(float)
                      + 128 * 33 * (int)sizeof(uint32_t);   // 101376
    cudaFuncSetAttribute(k1_lin_ln_silu,
                         cudaFuncAttributeMaxDynamicSharedMemorySize, k1_smem);
    cudaFuncSetAttribute(k2_cfconv_mma,
                         cudaFuncAttributeMaxDynamicSharedMemorySize, K2_SMEM);

    k1_lin_ln_silu<<<(BB * NN) / 64, 256, k1_smem>>>(s, W1, b1);
    k2_cfconv_mma<<<BB * 16, 256, K2_SMEM>>>(ev, mask, out);
}

// round 9
// speedup vs baseline: 1.1154x; 1.1007x over previous
#include <cuda_runtime.h>
#include <cuda_bf16.h>
#include <math.h>
#include <stdint.h>

#define BB 32
#define NN 512
#define HH 128

// h split-bf16 planes, [b][d][n] (transposed), row-contiguous in n. 4 MB each.
__device__ __nv_bfloat16 g_hBhi[BB * HH * NN];
__device__ __nv_bfloat16 g_hBlo[BB * HH * NN];

__device__ __forceinline__ uint32_t smem_u32(const void* p) {
    uint32_t a;
    asm("{ .reg .u64 t; cvta.to.shared.u64 t, %1; cvt.u32.u64 %0, t; }"
        : "=r"(a) : "l"(p));
    return a;
}

#define CP_ASYNC16(dst_u32, src_ptr) \
    asm volatile("cp.async.cg.shared.global [%0], [%1], 16;" \
                 :: "r"(dst_u32), "l"(src_ptr) : "memory")
#define CP_COMMIT() asm volatile("cp.async.commit_group;" ::: "memory")
#define CP_WAIT(n)  asm volatile("cp.async.wait_group %0;" :: "n"(n) : "memory")

// ---------------------------------------------------------------------------
// K1 (R6 version — conflict-free, measured 28.5us): h = silu(LN(s@W1^T+b1));
// 256 CTAs x 256 thr; each CTA: 64 rows as two 32-row tiles, W1T loaded once.
// ---------------------------------------------------------------------------
__global__ void __launch_bounds__(256)
k1_lin_ln_silu(const float* __restrict__ s,
               const float* __restrict__ W1,
               const float* __restrict__ b1) {
    extern __shared__ float smem[];
    float*    W1T = smem;                           // 128*132 floats
    float*    sT  = smem + 128 * 132;               // 128*33 floats (reused as hp)
    uint32_t* tr  = (uint32_t*)(smem + 128 * 132 + 128 * 33);  // 128*33 u32

    const int t    = threadIdx.x;
    const int row0 = blockIdx.x * 64;
    const int cg = t & 31;
    const int rg = t >> 5;

#pragma unroll 8
    for (int k = 0; k < 64; ++k) {
        int u = t + k * 256;
        int c = u >> 7, h = u & 127;
        W1T[h * 132 + c] = W1[u];
    }

    for (int rt = 0; rt < 2; ++rt) {
        const int rbase = row0 + rt * 32;
        __syncthreads();          // prev tile fully consumed
#pragma unroll 8
        for (int k = 0; k < 16; ++k) {
            int u = t + k * 256;
            int r = u >> 7, h = u & 127;
            sT[h * 33 + r] = s[rbase * 128 + u];
        }
        __syncthreads();

        float4 acc0 = make_float4(0.f, 0.f, 0.f, 0.f);
        float4 acc1 = acc0, acc2 = acc0, acc3 = acc0;

        const float4* W1T4 = (const float4*)W1T;
#pragma unroll 4
        for (int h = 0; h < 128; ++h) {
            float4 w = W1T4[h * 33 + cg];
            float a0 = sT[h * 33 + rg * 4 + 0];
            float a1 = sT[h * 33 + rg * 4 + 1];
            float a2 = sT[h * 33 + rg * 4 + 2];
            float a3 = sT[h * 33 + rg * 4 + 3];
            acc0.x += a0 * w.x; acc0.y += a0 * w.y; acc0.z += a0 * w.z; acc0.w += a0 * w.w;
            acc1.x += a1 * w.x; acc1.y += a1 * w.y; acc1.z += a1 * w.z; acc1.w += a1 * w.w;
            acc2.x += a2 * w.x; acc2.y += a2 * w.y; acc2.z += a2 * w.z; acc2.w += a2 * w.w;
            acc3.x += a3 * w.x; acc3.y += a3 * w.y; acc3.z += a3 * w.z; acc3.w += a3 * w.w;
        }
        {
            float4 bv = ((const float4*)b1)[cg];
            acc0.x += bv.x; acc0.y += bv.y; acc0.z += bv.z; acc0.w += bv.w;
            acc1.x += bv.x; acc1.y += bv.y; acc1.z += bv.z; acc1.w += bv.w;
            acc2.x += bv.x; acc2.y += bv.y; acc2.z += bv.z; acc2.w += bv.w;
            acc3.x += bv.x; acc3.y += bv.y; acc3.z += bv.z; acc3.w += bv.w;
        }

        __syncthreads();          // sT reads done -> reuse as hp
        float4* hp4 = (float4*)sT;    // [32 rows][32 float4]
        hp4[(rg * 4 + 0) * 32 + cg] = acc0;
        hp4[(rg * 4 + 1) * 32 + cg] = acc1;
        hp4[(rg * 4 + 2) * 32 + cg] = acc2;
        hp4[(rg * 4 + 3) * 32 + cg] = acc3;
        __syncthreads();

        const float inv128 = 1.0f / 128.0f;
#pragma unroll
        for (int rr = 0; rr < 4; ++rr) {
            int row = rg * 4 + rr;
            float4 x = hp4[row * 32 + cg];
            float sm = x.x + x.y + x.z + x.w;
            float sq = x.x * x.x + x.y * x.y + x.z * x.z + x.w * x.w;
#pragma unroll
            for (int o = 16; o > 0; o >>= 1) {
                sm += __shfl_xor_sync(0xFFFFFFFFu, sm, o);
                sq += __shfl_xor_sync(0xFFFFFFFFu, sq, o);
            }
            float mu  = sm * inv128;
            float var = sq * inv128 - mu * mu;
            float rs  = rsqrtf(var + 1e-5f);
            float y[4];
            y[0] = (x.x - mu) * rs; y[1] = (x.y - mu) * rs;
            y[2] = (x.z - mu) * rs; y[3] = (x.w - mu) * rs;
#pragma unroll
            for (int q = 0; q < 4; ++q) {
                float yv = y[q] / (1.0f + __expf(-y[q]));    // silu
                __nv_bfloat16 hi = __float2bfloat16(yv);
                __nv_bfloat16 lo = __float2bfloat16(yv - __bfloat162float(hi));
                uint32_t pk = (uint32_t)__bfloat16_as_ushort(hi)
                            | ((uint32_t)__bfloat16_as_ushort(lo) << 16);
                tr[(4 * cg + q) * 33 + row] = pk;
            }
        }
        __syncthreads();

        const int b  = row0 >> 9;
        const int n0 = (row0 & 511) + rt * 32;
#pragma unroll
        for (int k = 0; k < 8; ++k) {
            int u = t + k * 256;              // 0..2047
            int d = u >> 4, np = u & 15;
            uint32_t t0 = tr[d * 33 + 2 * np];
            uint32_t t1 = tr[d * 33 + 2 * np + 1];
            uint32_t hip = (t0 & 0xFFFFu) | (t1 << 16);
            uint32_t lop = (t0 >> 16) | (t1 & 0xFFFF0000u);
            int idx = ((b * 128 + d) * 512 + n0) / 2 + np;
            ((uint32_t*)g_hBhi)[idx] = hip;
            ((uint32_t*)g_hBlo)[idx] = lop;
        }
    }
}

// ---------------------------------------------------------------------------
// K2 (R7 version — measured 74.5us): fully-overlapped split-bf16 HMMA CFConv.
// grid: 32 b x 8 i-tiles (64 i) = 256 CTAs, 512 threads (16 warps 4m x 4n).
// Double-buffered conv tiles; no raw staging. Per phase ch:
//   issue cp.async B(ch+1) -> B[1-p];  LDG ev/mk(ch+1) half0 -> regs
//   MMA kb0,kb1 (from A[p],B[p]);  convert half0 -> A[1-p]; LDG half1
//   MMA kb2,kb3;  convert half1 -> A[1-p];  cp.wait; barrier
// smem: A[2][3c][2split][64 i][144B] = 110592 B; B[2][2split][128 d][144B]
//       @110592 = 73728 B.  Total 184320 B.
// ---------------------------------------------------------------------------
#define A_BUF_STRIDE 55296
#define A_C_STRIDE   18432
#define A_S_STRIDE   9216
#define SM_ROW       144
#define B_BASE       110592
#define B_BUF_STRIDE 36864
#define B_S_STRIDE   18432
#define K2_SMEM      184320

#define LDSM_X4(r, addr) \
    asm volatile("ldmatrix.sync.aligned.m8n8.x4.shared.b16 {%0,%1,%2,%3}, [%4];" \
                 : "=r"((r)[0]), "=r"((r)[1]), "=r"((r)[2]), "=r"((r)[3]) \
                 : "r"(addr))

#define MMA_BF16(acc, a, b0, b1) \
    asm volatile("mma.sync.aligned.m16n8k16.row.col.f32.bf16.bf16.f32 " \
                 "{%0,%1,%2,%3}, {%4,%5,%6,%7}, {%8,%9}, {%0,%1,%2,%3};" \
                 : "+f"((acc)[0]), "+f"((acc)[1]), "+f"((acc)[2]), "+f"((acc)[3]) \
                 : "r"((a)[0]), "r"((a)[1]), "r"((a)[2]), "r"((a)[3]), \
                   "r"(b0), "r"(b1))

__global__ void __launch_bounds__(512, 1)
k2_cfconv_mma(const float* __restrict__ ev,
              const float* __restrict__ mask,
              float* __restrict__ out) {
    extern __shared__ char smc[];
    const uint32_t smem_base = smem_u32(smc);
    const int t    = threadIdx.x;
    const int lane = t & 31;
    const int wid  = t >> 5;
    const int wm   = wid >> 2;     // 0..3: i-subtile of 16
    const int wn   = wid & 3;      // 0..3: d-subtile of 32
    const int b    = blockIdx.x >> 3;
    const int i0   = (blockIdx.x & 7) * 64;

    // convert ownership: thread -> (i, jb) ; covers 8 j for all 3 c
    const int cv_i  = t >> 3;
    const int cv_jb = t & 7;
    const float* ev_row = ev + ((size_t)((b * 512 + i0 + cv_i) * 512)) * 3 + cv_jb * 24;
    const float* mk_row = mask + (size_t)(b * 512 + i0 + cv_i) * 512 + cv_jb * 8;
    const uint32_t cv_dst = (uint32_t)(cv_i * SM_ROW + cv_jb * 16);

    float acc[3][4][4];
#pragma unroll
    for (int c = 0; c < 3; ++c)
#pragma unroll
        for (int nt = 0; nt < 4; ++nt)
#pragma unroll
            for (int q = 0; q < 4; ++q) acc[c][nt][q] = 0.0f;

    const uint32_t a_lane = (uint32_t)((wm * 16 + (lane & 15)) * SM_ROW + (lane >> 4) * 16);
    uint32_t b_lane[2];
#pragma unroll
    for (int q = 0; q < 2; ++q) {
        int n = wn * 32 + q * 16 + (lane & 7) + ((lane >> 4) & 1) * 8;
        b_lane[q] = (uint32_t)(B_BASE + n * SM_ROW + ((lane >> 3) & 1) * 16);
    }

    // B(ch) -> buffer pb via cp.async (2 splits x 128 d x 128B)
    auto issue_B = [&](int j0, int pb) {
#pragma unroll
        for (int p = t; p < 2048; p += 512) {
            int sp = p >> 10, r = p & 1023;
            int d = r >> 3, q = r & 7;
            const char* srcbase = sp ? (const char*)g_hBlo : (const char*)g_hBhi;
            const char* src = srcbase + ((size_t)((b * 128 + d) * 512 + j0) * 2) + q * 16;
            CP_ASYNC16(smem_base + B_BASE + pb * B_BUF_STRIDE + sp * B_S_STRIDE
                       + d * SM_ROW + q * 16, src);
        }
        CP_COMMIT();
    };

    // LDG one half (4 j) of this thread's (i, jb) block for chunk at j0
    auto ldg_half = [&](int j0, int h, float4* rev, float4& rmk) {
        const float4* ep = (const float4*)(ev_row + (size_t)j0 * 3 + h * 12);
        rev[0] = ep[0]; rev[1] = ep[1]; rev[2] = ep[2];
        rmk = *(const float4*)(mk_row + j0 + h * 4);
    };

    // convert one half into A[pa]
    auto convert_half = [&](int pa, int h, const float4* rev, const float4& rmk) {
        const float* evv = (const float*)rev;   // 12 floats: [j][c]
        float mv[4] = {rmk.x, rmk.y, rmk.z, rmk.w};
#pragma unroll
        for (int c = 0; c < 3; ++c) {
            uint32_t hi2[2], lo2[2];
#pragma unroll
            for (int pr = 0; pr < 2; ++pr) {
                float v0 = evv[(2 * pr)     * 3 + c] * mv[2 * pr];
                float v1 = evv[(2 * pr + 1) * 3 + c] * mv[2 * pr + 1];
                uint32_t vb0 = __float_as_uint(v0), vb1 = __float_as_uint(v1);
                uint32_t h0 = vb0 & 0xFFFF0000u, h1 = vb1 & 0xFFFF0000u;
                float l0f = v0 - __uint_as_float(h0);
                float l1f = v1 - __uint_as_float(h1);
                uint16_t l0 = __bfloat16_as_ushort(__float2bfloat16(l0f));
                uint16_t l1 = __bfloat16_as_ushort(__float2bfloat16(l1f));
                hi2[pr] = (h0 >> 16) | (h1 & 0xFFFF0000u);
                lo2[pr] = (uint32_t)l0 | ((uint32_t)l1 << 16);
            }
            char* dst = smc + pa * A_BUF_STRIDE + c * A_C_STRIDE + cv_dst + h * 8;
            *(uint2*)dst                = make_uint2(hi2[0], hi2[1]);
            *(uint2*)(dst + A_S_STRIDE) = make_uint2(lo2[0], lo2[1]);
        }
    };

    // one kb-step of MMAs from buffers (pa, pb)
    auto mma_kb = [&](int kb, int pa, int pb) {
        uint32_t afr[3][2][4];
        uint32_t bfr[2][2][4];
#pragma unroll
        for (int c = 0; c < 3; ++c)
#pragma unroll
            for (int s = 0; s < 2; ++s)
                LDSM_X4(afr[c][s], smem_base + pa * A_BUF_STRIDE + c * A_C_STRIDE
                                 + s * A_S_STRIDE + a_lane + kb * 32);
#pragma unroll
        for (int s = 0; s < 2; ++s)
#pragma unroll
            for (int q = 0; q < 2; ++q)
                LDSM_X4(bfr[s][q], smem_base + b_lane[q] + pb * B_BUF_STRIDE
                                 + s * B_S_STRIDE + kb * 32);
#pragma unroll
        for (int pass = 0; pass < 3; ++pass) {
            const int as = (pass == 1) ? 1 : 0;
            const int bs = (pass == 2) ? 1 : 0;
#pragma unroll
            for (int c = 0; c < 3; ++c)
#pragma unroll
                for (int nt = 0; nt < 4; ++nt) {
                    uint32_t* bbv = bfr[bs][nt >> 1];
                    MMA_BF16(acc[c][nt], afr[c][as],
                             bbv[(nt & 1) * 2], bbv[(nt & 1) * 2 + 1]);
                }
        }
    };

    // ---- prologue: fill A[0], B[0] for chunk 0
    {
        float4 rev[3]; float4 rmk;
        issue_B(0, 0);
        ldg_half(0, 0, rev, rmk);
        convert_half(0, 0, rev, rmk);
        ldg_half(0, 1, rev, rmk);
        convert_half(0, 1, rev, rmk);
        CP_WAIT(0);
        __syncthreads();
    }

#pragma unroll 1
    for (int ch = 0; ch < 8; ++ch) {
        const int p  = ch & 1;
        const int np = p ^ 1;
        const int nj = (ch + 1) * 64;
        float4 rev[3]; float4 rmk;

        if (ch < 7) {
            issue_B(nj, np);
            ldg_half(nj, 0, rev, rmk);
        }
        mma_kb(0, p, p);
        mma_kb(1, p, p);
        if (ch < 7) {
            convert_half(np, 0, rev, rmk);
            ldg_half(nj, 1, rev, rmk);
        }
        mma_kb(2, p, p);
        mma_kb(3, p, p);
        if (ch < 7) {
            convert_half(np, 1, rev, rmk);
        }
        CP_WAIT(0);
        __syncthreads();
    }

    // ---- epilogue: fragments -> out[b][i][c][d]
    const int r0 = i0 + wm * 16 + (lane >> 2);
    const int dq = wn * 32 + (lane & 3) * 2;
#pragma unroll
    for (int c = 0; c < 3; ++c) {
#pragma unroll
        for (int nt = 0; nt < 4; ++nt) {
            int d = dq + nt * 8;
            size_t o0 = ((size_t)(b * 512 + r0)     * 3 + c) * 128 + d;
            size_t o1 = ((size_t)(b * 512 + r0 + 8) * 3 + c) * 128 + d;
            *(float2*)(out + o0) = make_float2(acc[c][nt][0], acc[c][nt][1]);
            *(float2*)(out + o1) = make_float2(acc[c][nt][2], acc[c][nt][3]);
        }
    }
}

// ---------------------------------------------------------------------------
extern "C" void kernel_launch(void* const* d_in, const int* in_sizes, int n_in,
                              void* d_out, int out_size) {
    const float* s    = (const float*)d_in[0];   // (32,512,128)
    const float* ev   = (const float*)d_in[1];   // (32,512,512,3)
    const float* mask = (const float*)d_in[2];   // (32,512,512,1)
    const float* W1   = (const float*)d_in[3];   // (128,128)
    const float* b1   = (const float*)d_in[4];   // (128,)
    float* out = (float*)d_out;                  // (32,512,3,128)

    const int k1_smem = (128 * 132 + 128 * 33) * (int)sizeof(float)
                      + 128 * 33 * (int)sizeof(uint32_t);   // 101376
    cudaFuncSetAttribute(k1_lin_ln_silu,
                         cudaFuncAttributeMaxDynamicSharedMemorySize, k1_smem);
    cudaFuncSetAttribute(k2_cfconv_mma,
                         cudaFuncAttributeMaxDynamicSharedMemorySize, K2_SMEM);

    k1_lin_ln_silu<<<(BB * NN) / 64, 256, k1_smem>>>(s, W1, b1);
    k2_cfconv_mma<<<BB * 8, 512, K2_SMEM>>>(ev, mask, out);
}

// round 10
// speedup vs baseline: 1.2827x; 1.1500x over previous
#include <cuda_runtime.h>
#include <cuda_fp16.h>
#include <math.h>
#include <stdint.h>

#define BB 32
#define NN 512
#define HH 128

// h as single f16 plane, [b][d][n] (transposed), row-contiguous in n. 4 MB.
__device__ __half g_hB[BB * HH * NN];

__device__ __forceinline__ uint32_t smem_u32(const void* p) {
    uint32_t a;
    asm("{ .reg .u64 t; cvta.to.shared.u64 t, %1; cvt.u32.u64 %0, t; }"
        : "=r"(a) : "l"(p));
    return a;
}

#define CP_ASYNC16(dst_u32, src_ptr) \
    asm volatile("cp.async.cg.shared.global [%0], [%1], 16;" \
                 :: "r"(dst_u32), "l"(src_ptr) : "memory")
#define CP_COMMIT() asm volatile("cp.async.commit_group;" ::: "memory")
#define CP_WAIT(n)  asm volatile("cp.async.wait_group %0;" :: "n"(n) : "memory")

// ---------------------------------------------------------------------------
// K1: h = silu(LN(s @ W1^T + b1)); writes transposed f16 plane g_hB.
// 256 CTAs x 256 thr; each CTA: 64 rows as two 32-row tiles, W1T loaded once.
// ---------------------------------------------------------------------------
__global__ void __launch_bounds__(256)
k1_lin_ln_silu(const float* __restrict__ s,
               const float* __restrict__ W1,
               const float* __restrict__ b1) {
    extern __shared__ float smem[];
    float*    W1T = smem;                           // 128*132 floats
    float*    sT  = smem + 128 * 132;               // 128*33 floats (reused as hp)
    uint32_t* tr  = (uint32_t*)(smem + 128 * 132 + 128 * 33);  // 128*33 u32

    const int t    = threadIdx.x;
    const int row0 = blockIdx.x * 64;
    const int cg = t & 31;
    const int rg = t >> 5;

#pragma unroll 8
    for (int k = 0; k < 64; ++k) {
        int u = t + k * 256;
        int c = u >> 7, h = u & 127;
        W1T[h * 132 + c] = W1[u];
    }

    for (int rt = 0; rt < 2; ++rt) {
        const int rbase = row0 + rt * 32;
        __syncthreads();          // prev tile fully consumed
#pragma unroll 8
        for (int k = 0; k < 16; ++k) {
            int u = t + k * 256;
            int r = u >> 7, h = u & 127;
            sT[h * 33 + r] = s[rbase * 128 + u];
        }
        __syncthreads();

        float4 acc0 = make_float4(0.f, 0.f, 0.f, 0.f);
        float4 acc1 = acc0, acc2 = acc0, acc3 = acc0;

        const float4* W1T4 = (const float4*)W1T;
#pragma unroll 4
        for (int h = 0; h < 128; ++h) {
            float4 w = W1T4[h * 33 + cg];
            float a0 = sT[h * 33 + rg * 4 + 0];
            float a1 = sT[h * 33 + rg * 4 + 1];
            float a2 = sT[h * 33 + rg * 4 + 2];
            float a3 = sT[h * 33 + rg * 4 + 3];
            acc0.x += a0 * w.x; acc0.y += a0 * w.y; acc0.z += a0 * w.z; acc0.w += a0 * w.w;
            acc1.x += a1 * w.x; acc1.y += a1 * w.y; acc1.z += a1 * w.z; acc1.w += a1 * w.w;
            acc2.x += a2 * w.x; acc2.y += a2 * w.y; acc2.z += a2 * w.z; acc2.w += a2 * w.w;
            acc3.x += a3 * w.x; acc3.y += a3 * w.y; acc3.z += a3 * w.z; acc3.w += a3 * w.w;
        }
        {
            float4 bv = ((const float4*)b1)[cg];
            acc0.x += bv.x; acc0.y += bv.y; acc0.z += bv.z; acc0.w += bv.w;
            acc1.x += bv.x; acc1.y += bv.y; acc1.z += bv.z; acc1.w += bv.w;
            acc2.x += bv.x; acc2.y += bv.y; acc2.z += bv.z; acc2.w += bv.w;
            acc3.x += bv.x; acc3.y += bv.y; acc3.z += bv.z; acc3.w += bv.w;
        }

        __syncthreads();          // sT reads done -> reuse as hp
        float4* hp4 = (float4*)sT;    // [32 rows][32 float4]
        hp4[(rg * 4 + 0) * 32 + cg] = acc0;
        hp4[(rg * 4 + 1) * 32 + cg] = acc1;
        hp4[(rg * 4 + 2) * 32 + cg] = acc2;
        hp4[(rg * 4 + 3) * 32 + cg] = acc3;
        __syncthreads();

        const float inv128 = 1.0f / 128.0f;
#pragma unroll
        for (int rr = 0; rr < 4; ++rr) {
            int row = rg * 4 + rr;
            float4 x = hp4[row * 32 + cg];
            float sm = x.x + x.y + x.z + x.w;
            float sq = x.x * x.x + x.y * x.y + x.z * x.z + x.w * x.w;
#pragma unroll
            for (int o = 16; o > 0; o >>= 1) {
                sm += __shfl_xor_sync(0xFFFFFFFFu, sm, o);
                sq += __shfl_xor_sync(0xFFFFFFFFu, sq, o);
            }
            float mu  = sm * inv128;
            float var = sq * inv128 - mu * mu;
            float rs  = rsqrtf(var + 1e-5f);
            float y[4];
            y[0] = (x.x - mu) * rs; y[1] = (x.y - mu) * rs;
            y[2] = (x.z - mu) * rs; y[3] = (x.w - mu) * rs;
#pragma unroll
            for (int q = 0; q < 4; ++q) {
                float yv = y[q] / (1.0f + __expf(-y[q]));    // silu
                tr[(4 * cg + q) * 33 + row] =
                    (uint32_t)__half_as_ushort(__float2half_rn(yv));
            }
        }
        __syncthreads();

        const int b  = row0 >> 9;
        const int n0 = (row0 & 511) + rt * 32;
#pragma unroll
        for (int k = 0; k < 8; ++k) {
            int u = t + k * 256;              // 0..2047
            int d = u >> 4, np = u & 15;
            uint32_t t0 = tr[d * 33 + 2 * np];
            uint32_t t1 = tr[d * 33 + 2 * np + 1];
            uint32_t pk = (t0 & 0xFFFFu) | (t1 << 16);
            int idx = ((b * 128 + d) * 512 + n0) / 2 + np;
            ((uint32_t*)g_hB)[idx] = pk;
        }
    }
}

// ---------------------------------------------------------------------------
// K2: fully-overlapped f16-split HMMA CFConv (2 passes: a_hi*b + a_lo*b).
// grid: 32 b x 8 i-tiles (64 i) = 256 CTAs, 512 threads (16 warps 4m x 4n).
// smem: A[2buf][3c][2split][64 i][144B] = 110592 B
//       B[2buf][128 d][144B] @110592    =  36864 B.  Total 147456 B.
// Per phase ch (R7 schedule):
//   issue cp.async B(ch+1)->B[1-p]; LDG ev/mk(ch+1) half0 -> regs
//   MMA kb0,kb1; convert half0 -> A[1-p]; LDG half1
//   MMA kb2,kb3; convert half1 -> A[1-p]; cp.wait; barrier
// ---------------------------------------------------------------------------
#define A_BUF_STRIDE 55296
#define A_C_STRIDE   18432
#define A_S_STRIDE   9216
#define SM_ROW       144
#define B_BASE       110592
#define B_BUF_STRIDE 18432
#define K2_SMEM      147456

#define LDSM_X4(r, addr) \
    asm volatile("ldmatrix.sync.aligned.m8n8.x4.shared.b16 {%0,%1,%2,%3}, [%4];" \
                 : "=r"((r)[0]), "=r"((r)[1]), "=r"((r)[2]), "=r"((r)[3]) \
                 : "r"(addr))

#define MMA_F16(acc, a, b0, b1) \
    asm volatile("mma.sync.aligned.m16n8k16.row.col.f32.f16.f16.f32 " \
                 "{%0,%1,%2,%3}, {%4,%5,%6,%7}, {%8,%9}, {%0,%1,%2,%3};" \
                 : "+f"((acc)[0]), "+f"((acc)[1]), "+f"((acc)[2]), "+f"((acc)[3]) \
                 : "r"((a)[0]), "r"((a)[1]), "r"((a)[2]), "r"((a)[3]), \
                   "r"(b0), "r"(b1))

__global__ void __launch_bounds__(512, 1)
k2_cfconv_mma(const float* __restrict__ ev,
              const float* __restrict__ mask,
              float* __restrict__ out) {
    extern __shared__ char smc[];
    const uint32_t smem_base = smem_u32(smc);
    const int t    = threadIdx.x;
    const int lane = t & 31;
    const int wid  = t >> 5;
    const int wm   = wid >> 2;     // 0..3: i-subtile of 16
    const int wn   = wid & 3;      // 0..3: d-subtile of 32
    const int b    = blockIdx.x >> 3;
    const int i0   = (blockIdx.x & 7) * 64;

    // convert ownership: thread -> (i, jb) ; covers 8 j for all 3 c
    const int cv_i  = t >> 3;
    const int cv_jb = t & 7;
    const float* ev_row = ev + ((size_t)((b * 512 + i0 + cv_i) * 512)) * 3 + cv_jb * 24;
    const float* mk_row = mask + (size_t)(b * 512 + i0 + cv_i) * 512 + cv_jb * 8;
    const uint32_t cv_dst = (uint32_t)(cv_i * SM_ROW + cv_jb * 16);

    float acc[3][4][4];
#pragma unroll
    for (int c = 0; c < 3; ++c)
#pragma unroll
        for (int nt = 0; nt < 4; ++nt)
#pragma unroll
            for (int q = 0; q < 4; ++q) acc[c][nt][q] = 0.0f;

    const uint32_t a_lane = (uint32_t)((wm * 16 + (lane & 15)) * SM_ROW + (lane >> 4) * 16);
    uint32_t b_lane[2];
#pragma unroll
    for (int q = 0; q < 2; ++q) {
        int n = wn * 32 + q * 16 + (lane & 7) + ((lane >> 4) & 1) * 8;
        b_lane[q] = (uint32_t)(B_BASE + n * SM_ROW + ((lane >> 3) & 1) * 16);
    }

    // B(ch) -> buffer pb via cp.async (128 d rows x 128B = 1024 16B chunks)
    auto issue_B = [&](int j0, int pb) {
#pragma unroll
        for (int p = t; p < 1024; p += 512) {
            int d = p >> 3, q = p & 7;
            const char* src = (const char*)g_hB
                + ((size_t)((b * 128 + d) * 512 + j0) * 2) + q * 16;
            CP_ASYNC16(smem_base + B_BASE + pb * B_BUF_STRIDE + d * SM_ROW + q * 16, src);
        }
        CP_COMMIT();
    };

    // LDG one half (4 j) of this thread's (i, jb) block for chunk at j0
    auto ldg_half = [&](int j0, int h, float4* rev, float4& rmk) {
        const float4* ep = (const float4*)(ev_row + (size_t)j0 * 3 + h * 12);
        rev[0] = ep[0]; rev[1] = ep[1]; rev[2] = ep[2];
        rmk = *(const float4*)(mk_row + j0 + h * 4);
    };

    // convert one half into A[pa]: f16 hi + f16 lo split of m*ev
    auto convert_half = [&](int pa, int h, const float4* rev, const float4& rmk) {
        const float* evv = (const float*)rev;   // 12 floats: [j][c]
        float mv[4] = {rmk.x, rmk.y, rmk.z, rmk.w};
#pragma unroll
        for (int c = 0; c < 3; ++c) {
            uint32_t hi2[2], lo2[2];
#pragma unroll
            for (int pr = 0; pr < 2; ++pr) {
                float v0 = evv[(2 * pr)     * 3 + c] * mv[2 * pr];
                float v1 = evv[(2 * pr + 1) * 3 + c] * mv[2 * pr + 1];
                __half h0 = __float2half_rn(v0);
                __half h1 = __float2half_rn(v1);
                __half l0 = __float2half_rn(v0 - __half2float(h0));
                __half l1 = __float2half_rn(v1 - __half2float(h1));
                hi2[pr] = (uint32_t)__half_as_ushort(h0)
                        | ((uint32_t)__half_as_ushort(h1) << 16);
                lo2[pr] = (uint32_t)__half_as_ushort(l0)
                        | ((uint32_t)__half_as_ushort(l1) << 16);
            }
            char* dst = smc + pa * A_BUF_STRIDE + c * A_C_STRIDE + cv_dst + h * 8;
            *(uint2*)dst                = make_uint2(hi2[0], hi2[1]);
            *(uint2*)(dst + A_S_STRIDE) = make_uint2(lo2[0], lo2[1]);
        }
    };

    // one kb-step of MMAs from buffers (pa, pb): 2 passes (a_hi*b, a_lo*b)
    auto mma_kb = [&](int kb, int pa, int pb) {
        uint32_t afr[3][2][4];
        uint32_t bfr[2][4];
#pragma unroll
        for (int c = 0; c < 3; ++c)
#pragma unroll
            for (int s = 0; s < 2; ++s)
                LDSM_X4(afr[c][s], smem_base + pa * A_BUF_STRIDE + c * A_C_STRIDE
                                 + s * A_S_STRIDE + a_lane + kb * 32);
#pragma unroll
        for (int q = 0; q < 2; ++q)
            LDSM_X4(bfr[q], smem_base + b_lane[q] + pb * B_BUF_STRIDE + kb * 32);
#pragma unroll
        for (int pass = 0; pass < 2; ++pass) {
#pragma unroll
            for (int c = 0; c < 3; ++c)
#pragma unroll
                for (int nt = 0; nt < 4; ++nt) {
                    uint32_t* bbv = bfr[nt >> 1];
                    MMA_F16(acc[c][nt], afr[c][pass],
                            bbv[(nt & 1) * 2], bbv[(nt & 1) * 2 + 1]);
                }
        }
    };

    // ---- prologue: fill A[0], B[0] for chunk 0
    {
        float4 rev[3]; float4 rmk;
        issue_B(0, 0);
        ldg_half(0, 0, rev, rmk);
        convert_half(0, 0, rev, rmk);
        ldg_half(0, 1, rev, rmk);
        convert_half(0, 1, rev, rmk);
        CP_WAIT(0);
        __syncthreads();
    }

#pragma unroll 1
    for (int ch = 0; ch < 8; ++ch) {
        const int p  = ch & 1;
        const int np = p ^ 1;
        const int nj = (ch + 1) * 64;
        float4 rev[3]; float4 rmk;

        if (ch < 7) {
            issue_B(nj, np);
            ldg_half(nj, 0, rev, rmk);
        }
        mma_kb(0, p, p);
        mma_kb(1, p, p);
        if (ch < 7) {
            convert_half(np, 0, rev, rmk);
            ldg_half(nj, 1, rev, rmk);
        }
        mma_kb(2, p, p);
        mma_kb(3, p, p);
        if (ch < 7) {
            convert_half(np, 1, rev, rmk);
        }
        CP_WAIT(0);
        __syncthreads();
    }

    // ---- epilogue: fragments -> out[b][i][c][d]
    const int r0 = i0 + wm * 16 + (lane >> 2);
    const int dq = wn * 32 + (lane & 3) * 2;
#pragma unroll
    for (int c = 0; c < 3; ++c) {
#pragma unroll
        for (int nt = 0; nt < 4; ++nt) {
            int d = dq + nt * 8;
            size_t o0 = ((size_t)(b * 512 + r0)     * 3 + c) * 128 + d;
            size_t o1 = ((size_t)(b * 512 + r0 + 8) * 3 + c) * 128 + d;
            *(float2*)(out + o0) = make_float2(acc[c][nt][0], acc[c][nt][1]);
            *(float2*)(out + o1) = make_float2(acc[c][nt][2], acc[c][nt][3]);
        }
    }
}

// ---------------------------------------------------------------------------
extern "C" void kernel_launch(void* const* d_in, const int* in_sizes, int n_in,
                              void* d_out, int out_size) {
    const float* s    = (const float*)d_in[0];   // (32,512,128)
    const float* ev   = (const float*)d_in[1];   // (32,512,512,3)
    const float* mask = (const float*)d_in[2];   // (32,512,512,1)
    const float* W1   = (const float*)d_in[3];   // (128,128)
    const float* b1   = (const float*)d_in[4];   // (128,)
    float* out = (float*)d_out;                  // (32,512,3,128)

    const int k1_smem = (128 * 132 + 128 * 33) * (int)sizeof(float)
                      + 128 * 33 * (int)sizeof(uint32_t);   // 101376
    cudaFuncSetAttribute(k1_lin_ln_silu,
                         cudaFuncAttributeMaxDynamicSharedMemorySize, k1_smem);
    cudaFuncSetAttribute(k2_cfconv_mma,
                         cudaFuncAttributeMaxDynamicSharedMemorySize, K2_SMEM);

    k1_lin_ln_silu<<<(BB * NN) / 64, 256, k1_smem>>>(s, W1, b1);
    k2_cfconv_mma<<<BB * 8, 512, K2_SMEM>>>(ev, mask, out);
}

// round 11
// speedup vs baseline: 1.4061x; 1.0962x over previous
#include <cuda_runtime.h>
#include <cuda_fp16.h>
#include <math.h>
#include <stdint.h>

#define BB 32
#define NN 512
#define HH 128

// h as single f16 plane, [b][d][n] (transposed), row-contiguous in n. 4 MB.
__device__ __half g_hB[BB * HH * NN];

__device__ __forceinline__ uint32_t smem_u32(const void* p) {
    uint32_t a;
    asm("{ .reg .u64 t; cvta.to.shared.u64 t, %1; cvt.u32.u64 %0, t; }"
        : "=r"(a) : "l"(p));
    return a;
}

#define CP_ASYNC16(dst_u32, src_ptr) \
    asm volatile("cp.async.cg.shared.global [%0], [%1], 16;" \
                 :: "r"(dst_u32), "l"(src_ptr) : "memory")
#define CP_COMMIT() asm volatile("cp.async.commit_group;" ::: "memory")
#define CP_WAIT(n)  asm volatile("cp.async.wait_group %0;" :: "n"(n) : "memory")

#define LDSM_X4(r, addr) \
    asm volatile("ldmatrix.sync.aligned.m8n8.x4.shared.b16 {%0,%1,%2,%3}, [%4];" \
                 : "=r"((r)[0]), "=r"((r)[1]), "=r"((r)[2]), "=r"((r)[3]) \
                 : "r"(addr))

#define MMA_F16(acc, a, b0, b1) \
    asm volatile("mma.sync.aligned.m16n8k16.row.col.f32.f16.f16.f32 " \
                 "{%0,%1,%2,%3}, {%4,%5,%6,%7}, {%8,%9}, {%0,%1,%2,%3};" \
                 : "+f"((acc)[0]), "+f"((acc)[1]), "+f"((acc)[2]), "+f"((acc)[3]) \
                 : "r"((a)[0]), "r"((a)[1]), "r"((a)[2]), "r"((a)[3]), \
                   "r"(b0), "r"(b1))

// ---------------------------------------------------------------------------
// K1: h = silu(LN(s @ W1^T + b1)) via 3-pass split-f16 HMMA.
// 256 CTAs x 256 thr (8 warps, 4m x 2n); 64 rows/CTA.
// smem overlays (205312 B):
//   WHI/WLO f16 [128 d][272B]  @0 / 34816
//   SHI/SLO f16 [64 n][272B]   @69632 / 87040
//   HP f32 [64][132]           @104448 (W1-fp32 staging overlays 104448..169984)
//   TR u32 [128 d][66 n]       @138240
//   s-fp32 staging             @172032 (32768)
//   b1                         @204800 (512)
// ---------------------------------------------------------------------------
#define K1_ROWB 272
#define K1_WHI  0
#define K1_WLO  34816
#define K1_SHI  69632
#define K1_SLO  87040
#define K1_HP   104448
#define K1_STGW 104448
#define K1_TR   138240
#define K1_SSTG 172032
#define K1_B1   204800
#define K1_SMEM 205312

__global__ void __launch_bounds__(256)
k1_lin_ln_silu(const float* __restrict__ s,
               const float* __restrict__ W1,
               const float* __restrict__ b1) {
    extern __shared__ char smc[];
    const uint32_t smem_base = smem_u32(smc);
    const int t    = threadIdx.x;
    const int lane = t & 31;
    const int wid  = t >> 5;
    const int wm   = wid >> 1;     // 0..3: row subtile of 16
    const int wn   = wid & 1;      // 0..1: d subtile of 64
    const int row0 = blockIdx.x * 64;
    const int b    = blockIdx.x >> 3;
    const int n0   = (blockIdx.x & 7) * 64;

    float*    stgW = (float*)(smc + K1_STGW);
    float*    stgS = (float*)(smc + K1_SSTG);
    float*    b1s  = (float*)(smc + K1_B1);
    float*    hpf  = (float*)(smc + K1_HP);
    uint32_t* tr   = (uint32_t*)(smc + K1_TR);

    // ---- stage W1 (64KB), s tile (32KB), b1 (512B) via cp.async
#pragma unroll
    for (int k = 0; k < 16; ++k) {
        int u = t + k * 256;
        CP_ASYNC16(smem_base + K1_STGW + u * 16, (const char*)W1 + u * 16);
    }
#pragma unroll
    for (int k = 0; k < 8; ++k) {
        int u = t + k * 256;
        CP_ASYNC16(smem_base + K1_SSTG + u * 16,
                   (const char*)(s + (size_t)row0 * 128) + u * 16);
    }
    if (t < 32) CP_ASYNC16(smem_base + K1_B1 + t * 16, (const char*)b1 + t * 16);
    CP_COMMIT();
    CP_WAIT(0);
    __syncthreads();

    // ---- convert W1 -> f16 hi/lo planes [128 d][272B]
#pragma unroll
    for (int k = 0; k < 32; ++k) {
        int u = t + k * 256;           // 0..8191 pairs
        int d = u >> 6, kp = u & 63;
        float2 v = *(float2*)&stgW[d * 128 + 2 * kp];
        __half h0 = __float2half_rn(v.x), h1 = __float2half_rn(v.y);
        __half l0 = __float2half_rn(v.x - __half2float(h0));
        __half l1 = __float2half_rn(v.y - __half2float(h1));
        *(uint32_t*)(smc + K1_WHI + d * K1_ROWB + kp * 4) =
            (uint32_t)__half_as_ushort(h0) | ((uint32_t)__half_as_ushort(h1) << 16);
        *(uint32_t*)(smc + K1_WLO + d * K1_ROWB + kp * 4) =
            (uint32_t)__half_as_ushort(l0) | ((uint32_t)__half_as_ushort(l1) << 16);
    }
    // ---- convert s -> f16 hi/lo planes [64 n][272B]
#pragma unroll
    for (int k = 0; k < 16; ++k) {
        int u = t + k * 256;           // 0..4095 pairs
        int r = u >> 6, kp = u & 63;
        float2 v = *(float2*)&stgS[r * 128 + 2 * kp];
        __half h0 = __float2half_rn(v.x), h1 = __float2half_rn(v.y);
        __half l0 = __float2half_rn(v.x - __half2float(h0));
        __half l1 = __float2half_rn(v.y - __half2float(h1));
        *(uint32_t*)(smc + K1_SHI + r * K1_ROWB + kp * 4) =
            (uint32_t)__half_as_ushort(h0) | ((uint32_t)__half_as_ushort(h1) << 16);
        *(uint32_t*)(smc + K1_SLO + r * K1_ROWB + kp * 4) =
            (uint32_t)__half_as_ushort(l0) | ((uint32_t)__half_as_ushort(l1) << 16);
    }
    __syncthreads();

    // ---- MMA: warp tile m16 x n64, K=128 over 8 kb-steps, 3 passes
    float acc[8][4];
#pragma unroll
    for (int nt = 0; nt < 8; ++nt)
#pragma unroll
        for (int q = 0; q < 4; ++q) acc[nt][q] = 0.0f;

    const uint32_t aaddr = smem_base + K1_SHI
        + (uint32_t)((wm * 16 + (lane & 15)) * K1_ROWB + (lane >> 4) * 16);
    uint32_t baddr[4];
#pragma unroll
    for (int q = 0; q < 4; ++q) {
        int n = wn * 64 + q * 16 + (lane & 7) + ((lane >> 4) & 1) * 8;
        baddr[q] = smem_base + K1_WHI
            + (uint32_t)(n * K1_ROWB + ((lane >> 3) & 1) * 16);
    }

#pragma unroll
    for (int kb = 0; kb < 8; ++kb) {
        uint32_t afr[2][4];
        LDSM_X4(afr[0], aaddr + kb * 32);                    // s hi
        LDSM_X4(afr[1], aaddr + (K1_SLO - K1_SHI) + kb * 32);// s lo
        uint32_t bfr[2][4][4];
#pragma unroll
        for (int sp = 0; sp < 2; ++sp)
#pragma unroll
            for (int q = 0; q < 4; ++q)
                LDSM_X4(bfr[sp][q], baddr[q] + sp * (K1_WLO - K1_WHI) + kb * 32);
#pragma unroll
        for (int pass = 0; pass < 3; ++pass) {
            const int as = (pass == 1) ? 1 : 0;   // pass1: s_lo
            const int bs = (pass == 2) ? 1 : 0;   // pass2: W_lo
#pragma unroll
            for (int nt = 0; nt < 8; ++nt) {
                uint32_t* bbv = bfr[bs][nt >> 1];
                MMA_F16(acc[nt], afr[as],
                        bbv[(nt & 1) * 2], bbv[(nt & 1) * 2 + 1]);
            }
        }
    }

    // ---- fragments (+bias) -> hp[64][132] f32 (W1 staging dead)
    {
        int r = wm * 16 + (lane >> 2);
#pragma unroll
        for (int nt = 0; nt < 8; ++nt) {
            int d = wn * 64 + (nt >> 1) * 16 + (nt & 1) * 8 + (lane & 3) * 2;
            float2 bb = *(float2*)&b1s[d];
            *(float2*)&hpf[r * 132 + d] =
                make_float2(acc[nt][0] + bb.x, acc[nt][1] + bb.y);
            *(float2*)&hpf[(r + 8) * 132 + d] =
                make_float2(acc[nt][2] + bb.x, acc[nt][3] + bb.y);
        }
    }
    __syncthreads();

    // ---- LN + SiLU + f16 -> tr[128 d][66 n]
    const float inv128 = 1.0f / 128.0f;
    const float4* hp4 = (const float4*)hpf;   // row stride 33 float4
#pragma unroll
    for (int rr = 0; rr < 8; ++rr) {
        int row = wid * 8 + rr;
        float4 x = hp4[row * 33 + lane];
        float sm = x.x + x.y + x.z + x.w;
        float sq = x.x * x.x + x.y * x.y + x.z * x.z + x.w * x.w;
#pragma unroll
        for (int o = 16; o > 0; o >>= 1) {
            sm += __shfl_xor_sync(0xFFFFFFFFu, sm, o);
            sq += __shfl_xor_sync(0xFFFFFFFFu, sq, o);
        }
        float mu  = sm * inv128;
        float var = sq * inv128 - mu * mu;
        float rs  = rsqrtf(var + 1e-5f);
        float y[4];
        y[0] = (x.x - mu) * rs; y[1] = (x.y - mu) * rs;
        y[2] = (x.z - mu) * rs; y[3] = (x.w - mu) * rs;
#pragma unroll
        for (int q = 0; q < 4; ++q) {
            float yv = y[q] / (1.0f + __expf(-y[q]));    // silu
            tr[(4 * lane + q) * 66 + row] =
                (uint32_t)__half_as_ushort(__float2half_rn(yv));
        }
    }
    __syncthreads();

    // ---- packed transposed store: g_hB[b][d][n0..n0+64), n-pairs as u32
#pragma unroll
    for (int k = 0; k < 16; ++k) {
        int u = t + k * 256;              // 0..4095
        int d = u >> 5, np = u & 31;
        uint2 tp = *(uint2*)&tr[d * 66 + 2 * np];
        uint32_t pk = (tp.x & 0xFFFFu) | (tp.y << 16);
        ((uint32_t*)g_hB)[((b * 128 + d) * 512 + n0) / 2 + np] = pk;
    }
}

// ---------------------------------------------------------------------------
// K2 (R10, measured 61.5us): fully-overlapped f16-split HMMA CFConv.
// grid: 32 b x 8 i-tiles (64 i) = 256 CTAs, 512 threads (16 warps 4m x 4n).
// ---------------------------------------------------------------------------
#define A_BUF_STRIDE 55296
#define A_C_STRIDE   18432
#define A_S_STRIDE   9216
#define SM_ROW       144
#define B_BASE       110592
#define B_BUF_STRIDE 18432
#define K2_SMEM      147456

__global__ void __launch_bounds__(512, 1)
k2_cfconv_mma(const float* __restrict__ ev,
              const float* __restrict__ mask,
              float* __restrict__ out) {
    extern __shared__ char smc[];
    const uint32_t smem_base = smem_u32(smc);
    const int t    = threadIdx.x;
    const int lane = t & 31;
    const int wid  = t >> 5;
    const int wm   = wid >> 2;     // 0..3: i-subtile of 16
    const int wn   = wid & 3;      // 0..3: d-subtile of 32
    const int b    = blockIdx.x >> 3;
    const int i0   = (blockIdx.x & 7) * 64;

    const int cv_i  = t >> 3;
    const int cv_jb = t & 7;
    const float* ev_row = ev + ((size_t)((b * 512 + i0 + cv_i) * 512)) * 3 + cv_jb * 24;
    const float* mk_row = mask + (size_t)(b * 512 + i0 + cv_i) * 512 + cv_jb * 8;
    const uint32_t cv_dst = (uint32_t)(cv_i * SM_ROW + cv_jb * 16);

    float acc[3][4][4];
#pragma unroll
    for (int c = 0; c < 3; ++c)
#pragma unroll
        for (int nt = 0; nt < 4; ++nt)
#pragma unroll
            for (int q = 0; q < 4; ++q) acc[c][nt][q] = 0.0f;

    const uint32_t a_lane = (uint32_t)((wm * 16 + (lane & 15)) * SM_ROW + (lane >> 4) * 16);
    uint32_t b_lane[2];
#pragma unroll
    for (int q = 0; q < 2; ++q) {
        int n = wn * 32 + q * 16 + (lane & 7) + ((lane >> 4) & 1) * 8;
        b_lane[q] = (uint32_t)(B_BASE + n * SM_ROW + ((lane >> 3) & 1) * 16);
    }

    auto issue_B = [&](int j0, int pb) {
#pragma unroll
        for (int p = t; p < 1024; p += 512) {
            int d = p >> 3, q = p & 7;
            const char* src = (const char*)g_hB
                + ((size_t)((b * 128 + d) * 512 + j0) * 2) + q * 16;
            CP_ASYNC16(smem_base + B_BASE + pb * B_BUF_STRIDE + d * SM_ROW + q * 16, src);
        }
        CP_COMMIT();
    };

    auto ldg_half = [&](int j0, int h, float4* rev, float4& rmk) {
        const float4* ep = (const float4*)(ev_row + (size_t)j0 * 3 + h * 12);
        rev[0] = ep[0]; rev[1] = ep[1]; rev[2] = ep[2];
        rmk = *(const float4*)(mk_row + j0 + h * 4);
    };

    auto convert_half = [&](int pa, int h, const float4* rev, const float4& rmk) {
        const float* evv = (const float*)rev;   // 12 floats: [j][c]
        float mv[4] = {rmk.x, rmk.y, rmk.z, rmk.w};
#pragma unroll
        for (int c = 0; c < 3; ++c) {
            uint32_t hi2[2], lo2[2];
#pragma unroll
            for (int pr = 0; pr < 2; ++pr) {
                float v0 = evv[(2 * pr)     * 3 + c] * mv[2 * pr];
                float v1 = evv[(2 * pr + 1) * 3 + c] * mv[2 * pr + 1];
                __half h0 = __float2half_rn(v0);
                __half h1 = __float2half_rn(v1);
                __half l0 = __float2half_rn(v0 - __half2float(h0));
                __half l1 = __float2half_rn(v1 - __half2float(h1));
                hi2[pr] = (uint32_t)__half_as_ushort(h0)
                        | ((uint32_t)__half_as_ushort(h1) << 16);
                lo2[pr] = (uint32_t)__half_as_ushort(l0)
                        | ((uint32_t)__half_as_ushort(l1) << 16);
            }
            char* dst = smc + pa * A_BUF_STRIDE + c * A_C_STRIDE + cv_dst + h * 8;
            *(uint2*)dst                = make_uint2(hi2[0], hi2[1]);
            *(uint2*)(dst + A_S_STRIDE) = make_uint2(lo2[0], lo2[1]);
        }
    };

    auto mma_kb = [&](int kb, int pa, int pb) {
        uint32_t afr[3][2][4];
        uint32_t bfr[2][4];
#pragma unroll
        for (int c = 0; c < 3; ++c)
#pragma unroll
            for (int s = 0; s < 2; ++s)
                LDSM_X4(afr[c][s], smem_base + pa * A_BUF_STRIDE + c * A_C_STRIDE
                                 + s * A_S_STRIDE + a_lane + kb * 32);
#pragma unroll
        for (int q = 0; q < 2; ++q)
            LDSM_X4(bfr[q], smem_base + b_lane[q] + pb * B_BUF_STRIDE + kb * 32);
#pragma unroll
        for (int pass = 0; pass < 2; ++pass) {
#pragma unroll
            for (int c = 0; c < 3; ++c)
#pragma unroll
                for (int nt = 0; nt < 4; ++nt) {
                    uint32_t* bbv = bfr[nt >> 1];
                    MMA_F16(acc[c][nt], afr[c][pass],
                            bbv[(nt & 1) * 2], bbv[(nt & 1) * 2 + 1]);
                }
        }
    };

    // ---- prologue: fill A[0], B[0] for chunk 0
    {
        float4 rev[3]; float4 rmk;
        issue_B(0, 0);
        ldg_half(0, 0, rev, rmk);
        convert_half(0, 0, rev, rmk);
        ldg_half(0, 1, rev, rmk);
        convert_half(0, 1, rev, rmk);
        CP_WAIT(0);
        __syncthreads();
    }

#pragma unroll 1
    for (int ch = 0; ch < 8; ++ch) {
        const int p  = ch & 1;
        const int np = p ^ 1;
        const int nj = (ch + 1) * 64;
        float4 rev[3]; float4 rmk;

        if (ch < 7) {
            issue_B(nj, np);
            ldg_half(nj, 0, rev, rmk);
        }
        mma_kb(0, p, p);
        mma_kb(1, p, p);
        if (ch < 7) {
            convert_half(np, 0, rev, rmk);
            ldg_half(nj, 1, rev, rmk);
        }
        mma_kb(2, p, p);
        mma_kb(3, p, p);
        if (ch < 7) {
            convert_half(np, 1, rev, rmk);
        }
        CP_WAIT(0);
        __syncthreads();
    }

    // ---- epilogue: fragments -> out[b][i][c][d]
    const int r0 = i0 + wm * 16 + (lane >> 2);
    const int dq = wn * 32 + (lane & 3) * 2;
#pragma unroll
    for (int c = 0; c < 3; ++c) {
#pragma unroll
        for (int nt = 0; nt < 4; ++nt) {
            int d = dq + nt * 8;
            size_t o0 = ((size_t)(b * 512 + r0)     * 3 + c) * 128 + d;
            size_t o1 = ((size_t)(b * 512 + r0 + 8) * 3 + c) * 128 + d;
            *(float2*)(out + o0) = make_float2(acc[c][nt][0], acc[c][nt][1]);
            *(float2*)(out + o1) = make_float2(acc[c][nt][2], acc[c][nt][3]);
        }
    }
}

// ---------------------------------------------------------------------------
extern "C" void kernel_launch(void* const* d_in, const int* in_sizes, int n_in,
                              void* d_out, int out_size) {
    const float* s    = (const float*)d_in[0];   // (32,512,128)
    const float* ev   = (const float*)d_in[1];   // (32,512,512,3)
    const float* mask = (const float*)d_in[2];   // (32,512,512,1)
    const float* W1   = (const float*)d_in[3];   // (128,128)
    const float* b1   = (const float*)d_in[4];   // (128,)
    float* out = (float*)d_out;                  // (32,512,3,128)

    cudaFuncSetAttribute(k1_lin_ln_silu,
                         cudaFuncAttributeMaxDynamicSharedMemorySize, K1_SMEM);
    cudaFuncSetAttribute(k2_cfconv_mma,
                         cudaFuncAttributeMaxDynamicSharedMemorySize, K2_SMEM);

    k1_lin_ln_silu<<<(BB * NN) / 64, 256, K1_SMEM>>>(s, W1, b1);
    k2_cfconv_mma<<<BB * 8, 512, K2_SMEM>>>(ev, mask, out);
}

// round 12
// speedup vs baseline: 1.4908x; 1.0602x over previous
#include <cuda_runtime.h>
#include <cuda_fp16.h>
#include <math.h>
#include <stdint.h>

#define BB 32
#define NN 512
#define HH 128

// h as single f16 plane, [b][d][n] (transposed), row-contiguous in n. 4 MB.
__device__ __half g_hB[BB * HH * NN];
// W1 split-f16 planes, [d][k] row-major, 32 KB each.
__device__ __half g_W1hi[HH * HH];
__device__ __half g_W1lo[HH * HH];

__device__ __forceinline__ uint32_t smem_u32(const void* p) {
    uint32_t a;
    asm("{ .reg .u64 t; cvta.to.shared.u64 t, %1; cvt.u32.u64 %0, t; }"
        : "=r"(a) : "l"(p));
    return a;
}

#define CP_ASYNC16(dst_u32, src_ptr) \
    asm volatile("cp.async.cg.shared.global [%0], [%1], 16;" \
                 :: "r"(dst_u32), "l"(src_ptr) : "memory")
#define CP_COMMIT() asm volatile("cp.async.commit_group;" ::: "memory")
#define CP_WAIT(n)  asm volatile("cp.async.wait_group %0;" :: "n"(n) : "memory")

#define LDSM_X4(r, addr) \
    asm volatile("ldmatrix.sync.aligned.m8n8.x4.shared.b16 {%0,%1,%2,%3}, [%4];" \
                 : "=r"((r)[0]), "=r"((r)[1]), "=r"((r)[2]), "=r"((r)[3]) \
                 : "r"(addr))

#define MMA_F16(acc, a, b0, b1) \
    asm volatile("mma.sync.aligned.m16n8k16.row.col.f32.f16.f16.f32 " \
                 "{%0,%1,%2,%3}, {%4,%5,%6,%7}, {%8,%9}, {%0,%1,%2,%3};" \
                 : "+f"((acc)[0]), "+f"((acc)[1]), "+f"((acc)[2]), "+f"((acc)[3]) \
                 : "r"((a)[0]), "r"((a)[1]), "r"((a)[2]), "r"((a)[3]), \
                   "r"(b0), "r"(b1))

// ---------------------------------------------------------------------------
// K0: one-time W1 -> f16 hi/lo planes. 64 CTAs x 256 thr, 1 elem/thread.
// ---------------------------------------------------------------------------
__global__ void __launch_bounds__(256)
k0_w1_split(const float* __restrict__ W1) {
    int u = blockIdx.x * 256 + threadIdx.x;   // 0..16383
    float v = W1[u];
    __half h = __float2half_rn(v);
    g_W1hi[u] = h;
    g_W1lo[u] = __float2half_rn(v - __half2float(h));
}

// ---------------------------------------------------------------------------
// K1: h = silu(LN(s @ W1^T + b1)) via 3-pass split-f16 HMMA.
// W planes cp.async'd pre-split from K0. 256 CTAs x 256 thr; 64 rows/CTA.
// ---------------------------------------------------------------------------
#define K1_ROWB 272
#define K1_WHI  0
#define K1_WLO  34816
#define K1_SHI  69632
#define K1_SLO  87040
#define K1_HP   104448
#define K1_TR   138240
#define K1_SSTG 172032
#define K1_B1   204800
#define K1_SMEM 205312

__global__ void __launch_bounds__(256)
k1_lin_ln_silu(const float* __restrict__ s,
               const float* __restrict__ b1) {
    extern __shared__ char smc[];
    const uint32_t smem_base = smem_u32(smc);
    const int t    = threadIdx.x;
    const int lane = t & 31;
    const int wid  = t >> 5;
    const int wm   = wid >> 1;     // 0..3: row subtile of 16
    const int wn   = wid & 1;      // 0..1: d subtile of 64
    const int row0 = blockIdx.x * 64;
    const int b    = blockIdx.x >> 3;
    const int n0   = (blockIdx.x & 7) * 64;

    float*    stgS = (float*)(smc + K1_SSTG);
    float*    b1s  = (float*)(smc + K1_B1);
    float*    hpf  = (float*)(smc + K1_HP);
    uint32_t* tr   = (uint32_t*)(smc + K1_TR);

    // ---- stage W f16 planes (padded rows), s tile fp32, b1
#pragma unroll
    for (int k = 0; k < 8; ++k) {
        int u = t + k * 256;               // 0..2047 (16 chunks per 128 rows)
        int d = u >> 4, q = u & 15;
        CP_ASYNC16(smem_base + K1_WHI + d * K1_ROWB + q * 16,
                   (const char*)g_W1hi + u * 16);
        CP_ASYNC16(smem_base + K1_WLO + d * K1_ROWB + q * 16,
                   (const char*)g_W1lo + u * 16);
    }
#pragma unroll
    for (int k = 0; k < 8; ++k) {
        int u = t + k * 256;
        CP_ASYNC16(smem_base + K1_SSTG + u * 16,
                   (const char*)(s + (size_t)row0 * 128) + u * 16);
    }
    if (t < 32) CP_ASYNC16(smem_base + K1_B1 + t * 16, (const char*)b1 + t * 16);
    CP_COMMIT();
    CP_WAIT(0);
    __syncthreads();

    // ---- convert s -> f16 hi/lo planes [64 n][272B]
#pragma unroll
    for (int k = 0; k < 16; ++k) {
        int u = t + k * 256;           // 0..4095 pairs
        int r = u >> 6, kp = u & 63;
        float2 v = *(float2*)&stgS[r * 128 + 2 * kp];
        __half h0 = __float2half_rn(v.x), h1 = __float2half_rn(v.y);
        __half l0 = __float2half_rn(v.x - __half2float(h0));
        __half l1 = __float2half_rn(v.y - __half2float(h1));
        *(uint32_t*)(smc + K1_SHI + r * K1_ROWB + kp * 4) =
            (uint32_t)__half_as_ushort(h0) | ((uint32_t)__half_as_ushort(h1) << 16);
        *(uint32_t*)(smc + K1_SLO + r * K1_ROWB + kp * 4) =
            (uint32_t)__half_as_ushort(l0) | ((uint32_t)__half_as_ushort(l1) << 16);
    }
    __syncthreads();

    // ---- MMA: warp tile m16 x n64, K=128 over 8 kb-steps, 3 passes
    float acc[8][4];
#pragma unroll
    for (int nt = 0; nt < 8; ++nt)
#pragma unroll
        for (int q = 0; q < 4; ++q) acc[nt][q] = 0.0f;

    const uint32_t aaddr = smem_base + K1_SHI
        + (uint32_t)((wm * 16 + (lane & 15)) * K1_ROWB + (lane >> 4) * 16);
    uint32_t baddr[4];
#pragma unroll
    for (int q = 0; q < 4; ++q) {
        int n = wn * 64 + q * 16 + (lane & 7) + ((lane >> 4) & 1) * 8;
        baddr[q] = smem_base + K1_WHI
            + (uint32_t)(n * K1_ROWB + ((lane >> 3) & 1) * 16);
    }

#pragma unroll
    for (int kb = 0; kb < 8; ++kb) {
        uint32_t afr[2][4];
        LDSM_X4(afr[0], aaddr + kb * 32);                    // s hi
        LDSM_X4(afr[1], aaddr + (K1_SLO - K1_SHI) + kb * 32);// s lo
        uint32_t bfr[2][4][4];
#pragma unroll
        for (int sp = 0; sp < 2; ++sp)
#pragma unroll
            for (int q = 0; q < 4; ++q)
                LDSM_X4(bfr[sp][q], baddr[q] + sp * (K1_WLO - K1_WHI) + kb * 32);
#pragma unroll
        for (int pass = 0; pass < 3; ++pass) {
            const int as = (pass == 1) ? 1 : 0;
            const int bs = (pass == 2) ? 1 : 0;
#pragma unroll
            for (int nt = 0; nt < 8; ++nt) {
                uint32_t* bbv = bfr[bs][nt >> 1];
                MMA_F16(acc[nt], afr[as],
                        bbv[(nt & 1) * 2], bbv[(nt & 1) * 2 + 1]);
            }
        }
    }

    // ---- fragments (+bias) -> hp[64][132] f32
    {
        int r = wm * 16 + (lane >> 2);
#pragma unroll
        for (int nt = 0; nt < 8; ++nt) {
            int d = wn * 64 + (nt >> 1) * 16 + (nt & 1) * 8 + (lane & 3) * 2;
            float2 bb = *(float2*)&b1s[d];
            *(float2*)&hpf[r * 132 + d] =
                make_float2(acc[nt][0] + bb.x, acc[nt][1] + bb.y);
            *(float2*)&hpf[(r + 8) * 132 + d] =
                make_float2(acc[nt][2] + bb.x, acc[nt][3] + bb.y);
        }
    }
    __syncthreads();

    // ---- LN + SiLU + f16 -> tr[128 d][66 n]
    const float inv128 = 1.0f / 128.0f;
    const float4* hp4 = (const float4*)hpf;
#pragma unroll
    for (int rr = 0; rr < 8; ++rr) {
        int row = wid * 8 + rr;
        float4 x = hp4[row * 33 + lane];
        float sm = x.x + x.y + x.z + x.w;
        float sq = x.x * x.x + x.y * x.y + x.z * x.z + x.w * x.w;
#pragma unroll
        for (int o = 16; o > 0; o >>= 1) {
            sm += __shfl_xor_sync(0xFFFFFFFFu, sm, o);
            sq += __shfl_xor_sync(0xFFFFFFFFu, sq, o);
        }
        float mu  = sm * inv128;
        float var = sq * inv128 - mu * mu;
        float rs  = rsqrtf(var + 1e-5f);
        float y[4];
        y[0] = (x.x - mu) * rs; y[1] = (x.y - mu) * rs;
        y[2] = (x.z - mu) * rs; y[3] = (x.w - mu) * rs;
#pragma unroll
        for (int q = 0; q < 4; ++q) {
            float yv = y[q] / (1.0f + __expf(-y[q]));    // silu
            tr[(4 * lane + q) * 66 + row] =
                (uint32_t)__half_as_ushort(__float2half_rn(yv));
        }
    }
    __syncthreads();

    // ---- packed transposed store
#pragma unroll
    for (int k = 0; k < 16; ++k) {
        int u = t + k * 256;              // 0..4095
        int d = u >> 5, np = u & 31;
        uint2 tp = *(uint2*)&tr[d * 66 + 2 * np];
        uint32_t pk = (tp.x & 0xFFFFu) | (tp.y << 16);
        ((uint32_t*)g_hB)[((b * 128 + d) * 512 + n0) / 2 + np] = pk;
    }
}

// ---------------------------------------------------------------------------
// K2: fully-overlapped f16-split HMMA CFConv, 2 CTAs/SM.
// grid: 32 b x 16 i-tiles (32 i) = 512 CTAs, 256 threads (8 warps 2m x 4n).
// smem (92160 B/CTA, 2/SM):
//   A[2buf][3c][2split][32 i][144B] = 55296 B
//   B[2buf][128 d][144B] @55296     = 36864 B
// R7 schedule preserved: fill(ch+1) interleaved inside MMA(ch).
// ---------------------------------------------------------------------------
#define A_BUF_STRIDE 27648
#define A_C_STRIDE   9216
#define A_S_STRIDE   4608
#define SM_ROW       144
#define B_BASE       55296
#define B_BUF_STRIDE 18432
#define K2_SMEM      92160

__global__ void __launch_bounds__(256, 2)
k2_cfconv_mma(const float* __restrict__ ev,
              const float* __restrict__ mask,
              float* __restrict__ out) {
    extern __shared__ char smc[];
    const uint32_t smem_base = smem_u32(smc);
    const int t    = threadIdx.x;
    const int lane = t & 31;
    const int wid  = t >> 5;
    const int wm   = wid >> 2;     // 0..1: i-subtile of 16
    const int wn   = wid & 3;      // 0..3: d-subtile of 32
    const int b    = blockIdx.x >> 4;
    const int i0   = (blockIdx.x & 15) * 32;

    // convert ownership: thread -> (i, jb); covers 8 j for all 3 c
    const int cv_i  = t >> 3;      // 0..31
    const int cv_jb = t & 7;
    const float* ev_row = ev + ((size_t)((b * 512 + i0 + cv_i) * 512)) * 3 + cv_jb * 24;
    const float* mk_row = mask + (size_t)(b * 512 + i0 + cv_i) * 512 + cv_jb * 8;
    const uint32_t cv_dst = (uint32_t)(cv_i * SM_ROW + cv_jb * 16);

    float acc[3][4][4];
#pragma unroll
    for (int c = 0; c < 3; ++c)
#pragma unroll
        for (int nt = 0; nt < 4; ++nt)
#pragma unroll
            for (int q = 0; q < 4; ++q) acc[c][nt][q] = 0.0f;

    const uint32_t a_lane = (uint32_t)((wm * 16 + (lane & 15)) * SM_ROW + (lane >> 4) * 16);
    uint32_t b_lane[2];
#pragma unroll
    for (int q = 0; q < 2; ++q) {
        int n = wn * 32 + q * 16 + (lane & 7) + ((lane >> 4) & 1) * 8;
        b_lane[q] = (uint32_t)(B_BASE + n * SM_ROW + ((lane >> 3) & 1) * 16);
    }

    // B(ch) -> buffer pb via cp.async (128 d rows x 128B = 1024 16B chunks)
    auto issue_B = [&](int j0, int pb) {
#pragma unroll
        for (int p = t; p < 1024; p += 256) {
            int d = p >> 3, q = p & 7;
            const char* src = (const char*)g_hB
                + ((size_t)((b * 128 + d) * 512 + j0) * 2) + q * 16;
            CP_ASYNC16(smem_base + B_BASE + pb * B_BUF_STRIDE + d * SM_ROW + q * 16, src);
        }
        CP_COMMIT();
    };

    auto ldg_half = [&](int j0, int h, float4* rev, float4& rmk) {
        const float4* ep = (const float4*)(ev_row + (size_t)j0 * 3 + h * 12);
        rev[0] = ep[0]; rev[1] = ep[1]; rev[2] = ep[2];
        rmk = *(const float4*)(mk_row + j0 + h * 4);
    };

    auto convert_half = [&](int pa, int h, const float4* rev, const float4& rmk) {
        const float* evv = (const float*)rev;   // 12 floats: [j][c]
        float mv[4] = {rmk.x, rmk.y, rmk.z, rmk.w};
#pragma unroll
        for (int c = 0; c < 3; ++c) {
            uint32_t hi2[2], lo2[2];
#pragma unroll
            for (int pr = 0; pr < 2; ++pr) {
                float v0 = evv[(2 * pr)     * 3 + c] * mv[2 * pr];
                float v1 = evv[(2 * pr + 1) * 3 + c] * mv[2 * pr + 1];
                __half h0 = __float2half_rn(v0);
                __half h1 = __float2half_rn(v1);
                __half l0 = __float2half_rn(v0 - __half2float(h0));
                __half l1 = __float2half_rn(v1 - __half2float(h1));
                hi2[pr] = (uint32_t)__half_as_ushort(h0)
                        | ((uint32_t)__half_as_ushort(h1) << 16);
                lo2[pr] = (uint32_t)__half_as_ushort(l0)
                        | ((uint32_t)__half_as_ushort(l1) << 16);
            }
            char* dst = smc + pa * A_BUF_STRIDE + c * A_C_STRIDE + cv_dst + h * 8;
            *(uint2*)dst                = make_uint2(hi2[0], hi2[1]);
            *(uint2*)(dst + A_S_STRIDE) = make_uint2(lo2[0], lo2[1]);
        }
    };

    auto mma_kb = [&](int kb, int pa, int pb) {
        uint32_t afr[3][2][4];
        uint32_t bfr[2][4];
#pragma unroll
        for (int c = 0; c < 3; ++c)
#pragma unroll
            for (int s = 0; s < 2; ++s)
                LDSM_X4(afr[c][s], smem_base + pa * A_BUF_STRIDE + c * A_C_STRIDE
                                 + s * A_S_STRIDE + a_lane + kb * 32);
#pragma unroll
        for (int q = 0; q < 2; ++q)
            LDSM_X4(bfr[q], smem_base + b_lane[q] + pb * B_BUF_STRIDE + kb * 32);
#pragma unroll
        for (int pass = 0; pass < 2; ++pass) {
#pragma unroll
            for (int c = 0; c < 3; ++c)
#pragma unroll
                for (int nt = 0; nt < 4; ++nt) {
                    uint32_t* bbv = bfr[nt >> 1];
                    MMA_F16(acc[c][nt], afr[c][pass],
                            bbv[(nt & 1) * 2], bbv[(nt & 1) * 2 + 1]);
                }
        }
    };

    // ---- prologue: fill A[0], B[0] for chunk 0
    {
        float4 rev[3]; float4 rmk;
        issue_B(0, 0);
        ldg_half(0, 0, rev, rmk);
        convert_half(0, 0, rev, rmk);
        ldg_half(0, 1, rev, rmk);
        convert_half(0, 1, rev, rmk);
        CP_WAIT(0);
        __syncthreads();
    }

#pragma unroll 1
    for (int ch = 0; ch < 8; ++ch) {
        const int p  = ch & 1;
        const int np = p ^ 1;
        const int nj = (ch + 1) * 64;
        float4 rev[3]; float4 rmk;

        if (ch < 7) {
            issue_B(nj, np);
            ldg_half(nj, 0, rev, rmk);
        }
        mma_kb(0, p, p);
        mma_kb(1, p, p);
        if (ch < 7) {
            convert_half(np, 0, rev, rmk);
            ldg_half(nj, 1, rev, rmk);
        }
        mma_kb(2, p, p);
        mma_kb(3, p, p);
        if (ch < 7) {
            convert_half(np, 1, rev, rmk);
        }
        CP_WAIT(0);
        __syncthreads();
    }

    // ---- epilogue: fragments -> out[b][i][c][d]
    const int r0 = i0 + wm * 16 + (lane >> 2);
    const int dq = wn * 32 + (lane & 3) * 2;
#pragma unroll
    for (int c = 0; c < 3; ++c) {
#pragma unroll
        for (int nt = 0; nt < 4; ++nt) {
            int d = dq + nt * 8;
            size_t o0 = ((size_t)(b * 512 + r0)     * 3 + c) * 128 + d;
            size_t o1 = ((size_t)(b * 512 + r0 + 8) * 3 + c) * 128 + d;
            *(float2*)(out + o0) = make_float2(acc[c][nt][0], acc[c][nt][1]);
            *(float2*)(out + o1) = make_float2(acc[c][nt][2], acc[c][nt][3]);
        }
    }
}

// ---------------------------------------------------------------------------
extern "C" void kernel_launch(void* const* d_in, const int* in_sizes, int n_in,
                              void* d_out, int out_size) {
    const float* s    = (const float*)d_in[0];   // (32,512,128)
    const float* ev   = (const float*)d_in[1];   // (32,512,512,3)
    const float* mask = (const float*)d_in[2];   // (32,512,512,1)
    const float* W1   = (const float*)d_in[3];   // (128,128)
    const float* b1   = (const float*)d_in[4];   // (128,)
    float* out = (float*)d_out;                  // (32,512,3,128)

    cudaFuncSetAttribute(k1_lin_ln_silu,
                         cudaFuncAttributeMaxDynamicSharedMemorySize, K1_SMEM);
    cudaFuncSetAttribute(k2_cfconv_mma,
                         cudaFuncAttributeMaxDynamicSharedMemorySize, K2_SMEM);

    k0_w1_split<<<64, 256>>>(W1);
    k1_lin_ln_silu<<<(BB * NN) / 64, 256, K1_SMEM>>>(s, b1);
    k2_cfconv_mma<<<BB * 16, 256, K2_SMEM>>>(ev, mask, out);
}